// round 7
// baseline (speedup 1.0000x reference)
#include <cuda_runtime.h>
#include <cuda_fp16.h>
#include <math.h>
#include <stdint.h>

// ---------------------------------------------------------------------------
// CSTreeLSTM on GB300: split-fp16 HMMA GEMMs.
// C = (Ah+Al)(Bh+Bl)^T ~= AhBh [f32 acc] + (AhBl + AlBh) [f16 acc].
// Tree: 16-ary, depth 4, IN=HID=512. Levels 1,16,256,4096,65536
// (offsets 0,1,17,273,4369; total 69905).
// ---------------------------------------------------------------------------

#define IN_DIM 512
#define HID    512
#define NLEAF  65536
#define NTOT   69905

typedef __half hlf;

// ------------------------------ device scratch ------------------------------
__device__ __align__(128) float g_C [NTOT * HID];
__device__ __align__(128) float g_H [NTOT * HID];
__device__ __align__(128) float g_FH[NTOT * HID];
__device__ __align__(128) float g_G [4096 * 2048];   // node-level gates only

__device__ __align__(128) hlf g_Xh [NLEAF * IN_DIM];
__device__ __align__(128) hlf g_Xl [NLEAF * IN_DIM];
__device__ __align__(128) hlf g_Ch [NTOT * HID];
__device__ __align__(128) hlf g_Cl [NTOT * HID];
__device__ __align__(128) hlf g_XHh[4096 * 1024];
__device__ __align__(128) hlf g_XHl[4096 * 1024];

__device__ __align__(128) hlf g_Wnh[2048 * 1024];
__device__ __align__(128) hlf g_Wnl[2048 * 1024];
__device__ __align__(128) hlf g_Wlh[1536 * 512];
__device__ __align__(128) hlf g_Wll[1536 * 512];
__device__ __align__(128) hlf g_Wfhh[512 * 512];
__device__ __align__(128) hlf g_Wfhl[512 * 512];
__device__ float g_bleaf[1536];
__device__ float g_bnode[2048];

__device__ __forceinline__ float sigf(float x) { return 1.f / (1.f + expf(-x)); }

__device__ __forceinline__ void split1(float v, hlf& h, hlf& l) {
    h = __float2half_rn(v);
    l = __float2half_rn(v - __half2float(h));
}

// ------------------------------ PTX helpers ---------------------------------
__device__ __forceinline__ uint32_t smem_u32(const void* p) {
    uint32_t a;
    asm("{ .reg .u64 t; cvta.to.shared.u64 t, %1; cvt.u32.u64 %0, t; }" : "=r"(a) : "l"(p));
    return a;
}

__device__ __forceinline__ void cp16(uint32_t dst, const void* src) {
    asm volatile("cp.async.cg.shared.global [%0], [%1], 16;" :: "r"(dst), "l"(src));
}
#define CP_COMMIT() asm volatile("cp.async.commit_group;" ::: "memory")

__device__ __forceinline__ void ldsm4(uint32_t* r, uint32_t addr) {
    asm volatile("ldmatrix.sync.aligned.m8n8.x4.shared.b16 {%0,%1,%2,%3}, [%4];"
                 : "=r"(r[0]), "=r"(r[1]), "=r"(r[2]), "=r"(r[3]) : "r"(addr));
}
__device__ __forceinline__ void ldsm2(uint32_t* r, uint32_t addr) {
    asm volatile("ldmatrix.sync.aligned.m8n8.x2.shared.b16 {%0,%1}, [%2];"
                 : "=r"(r[0]), "=r"(r[1]) : "r"(addr));
}
// fp32-accumulator MMA (main term)
__device__ __forceinline__ void mma16816(float* d, const uint32_t* a, const uint32_t* b) {
    asm volatile(
        "mma.sync.aligned.m16n8k16.row.col.f32.f16.f16.f32 "
        "{%0,%1,%2,%3}, {%4,%5,%6,%7}, {%8,%9}, {%0,%1,%2,%3};"
        : "+f"(d[0]), "+f"(d[1]), "+f"(d[2]), "+f"(d[3])
        : "r"(a[0]), "r"(a[1]), "r"(a[2]), "r"(a[3]), "r"(b[0]), "r"(b[1]));
}
// fp16-accumulator MMA (correction terms)
__device__ __forceinline__ void mma16816h(uint32_t* d, const uint32_t* a, const uint32_t* b) {
    asm volatile(
        "mma.sync.aligned.m16n8k16.row.col.f16.f16.f16.f16 "
        "{%0,%1}, {%2,%3,%4,%5}, {%6,%7}, {%0,%1};"
        : "+r"(d[0]), "+r"(d[1])
        : "r"(a[0]), "r"(a[1]), "r"(a[2]), "r"(a[3]), "r"(b[0]), "r"(b[1]));
}

// ---------------------------------------------------------------------------
// Fused leaf kernel. CTA tile: 128(M) x 64(h), 3 gates. 512 threads,
// 16 warps, warp tile 32x16 per gate, BK=32, 3 stages. M%128==0, K=512.
// ---------------------------------------------------------------------------
#define LF_PITCH 80
#define LF_AT (128 * LF_PITCH)
#define LF_BT (64 * LF_PITCH)
#define LF_STAGE (2 * LF_AT + 6 * LF_BT)
#define LF_SMEM (3 * LF_STAGE + 128)

__global__ __launch_bounds__(512)
void leaf_fused(const hlf* __restrict__ Ah, const hlf* __restrict__ Al) {
    extern __shared__ char smem_raw[];
    const uint32_t sbase = (smem_u32(smem_raw) + 127) & ~127u;

    const int tid  = threadIdx.x;
    const int lane = tid & 31;
    const int wid  = tid >> 5;
    const int wm   = wid >> 2;
    const int wn   = wid & 3;
    const int bm   = blockIdx.y * 128;
    const int bh   = blockIdx.x * 64;
    const int K    = 512;
    const int NC   = 16;

    const int ag = lane >> 3, ai = lane & 7;
    const int a_row = ai + (ag & 1) * 8;
    const int a_kb  = (ag >> 1) * 16;
    const int b_row = lane & 7;
    const int b_kb  = ((lane >> 3) & 1) * 16;

    float    acc [3][2][2][4];
    uint32_t corr[3][2][2][2];
#pragma unroll
    for (int g = 0; g < 3; g++)
#pragma unroll
        for (int mt = 0; mt < 2; mt++)
#pragma unroll
            for (int nt = 0; nt < 2; nt++) {
#pragma unroll
                for (int j = 0; j < 4; j++) acc[g][mt][nt][j] = 0.f;
                corr[g][mt][nt][0] = 0u; corr[g][mt][nt][1] = 0u;
            }

    auto load_chunk = [&](int c, int s) {
        const uint32_t sb = sbase + s * LF_STAGE;
        const int k0 = c << 5;
        {
            int row = tid >> 2, cb = tid & 3;
            size_t aoff = (size_t)(bm + row) * K + k0 + cb * 8;
            uint32_t so = row * LF_PITCH + cb * 16;
            cp16(sb + so,         Ah + aoff);
            cp16(sb + LF_AT + so, Al + aoff);
        }
#pragma unroll
        for (int i = 0; i < 2; ++i) {
            int p = tid + i * 512;
            if (p < 768) {
                int g = p >> 8, pp = p & 255;
                int row = pp >> 2, cb = pp & 3;
                size_t woff = (size_t)(g * 512 + bh + row) * 512 + k0 + cb * 8;
                uint32_t base = sb + 2 * LF_AT + g * 2 * LF_BT;
                uint32_t so = row * LF_PITCH + cb * 16;
                cp16(base + so,         g_Wlh + woff);
                cp16(base + LF_BT + so, g_Wll + woff);
            }
        }
        CP_COMMIT();
    };

    load_chunk(0, 0);
    load_chunk(1, 1);

    for (int c = 0; c < NC; ++c) {
        if (c + 2 < NC) load_chunk(c + 2, (c + 2) % 3);

        if (c + 2 < NC)      asm volatile("cp.async.wait_group 2;" ::: "memory");
        else if (c + 1 < NC) asm volatile("cp.async.wait_group 1;" ::: "memory");
        else                 asm volatile("cp.async.wait_group 0;" ::: "memory");
        __syncthreads();

        const uint32_t sb = sbase + (c % 3) * LF_STAGE;

#pragma unroll
        for (int ks = 0; ks < 2; ++ks) {
            const int kb = ks * 32;
            uint32_t ah[2][4], al[2][4];
#pragma unroll
            for (int mt = 0; mt < 2; ++mt) {
                uint32_t ro = (wm * 32 + mt * 16 + a_row) * LF_PITCH + a_kb + kb;
                ldsm4(ah[mt], sb + ro);
                ldsm4(al[mt], sb + LF_AT + ro);
            }
#pragma unroll
            for (int g = 0; g < 3; ++g) {
                const uint32_t base = sb + 2 * LF_AT + g * 2 * LF_BT;
                uint32_t bhf[2][2], blf[2][2];
#pragma unroll
                for (int nt = 0; nt < 2; ++nt) {
                    uint32_t ro = (wn * 16 + nt * 8 + b_row) * LF_PITCH + b_kb + kb;
                    ldsm2(bhf[nt], base + ro);
                    ldsm2(blf[nt], base + LF_BT + ro);
                }
#pragma unroll
                for (int mt = 0; mt < 2; ++mt)
#pragma unroll
                    for (int nt = 0; nt < 2; ++nt) {
                        mma16816 (acc [g][mt][nt], ah[mt], bhf[nt]);
                        mma16816h(corr[g][mt][nt], ah[mt], blf[nt]);
                        mma16816h(corr[g][mt][nt], al[mt], bhf[nt]);
                    }
            }
        }
        __syncthreads();
    }

    const int r0 = lane >> 2;
    const int q2 = (lane & 3) * 2;
#pragma unroll
    for (int mt = 0; mt < 2; ++mt) {
#pragma unroll
        for (int nt = 0; nt < 2; ++nt) {
            int col = bh + wn * 16 + nt * 8 + q2;
            float bi0 = g_bleaf[col],        bi1 = g_bleaf[col + 1];
            float bo0 = g_bleaf[512 + col],  bo1 = g_bleaf[512 + col + 1];
            float bu0 = g_bleaf[1024 + col], bu1 = g_bleaf[1024 + col + 1];
#pragma unroll
            for (int hf = 0; hf < 2; ++hf) {
                int row = bm + wm * 32 + mt * 16 + r0 + hf * 8;
                float2 ci = __half22float2(((__half2*)corr[0][mt][nt])[hf]);
                float2 co = __half22float2(((__half2*)corr[1][mt][nt])[hf]);
                float2 cu = __half22float2(((__half2*)corr[2][mt][nt])[hf]);
                float i0 = sigf(acc[0][mt][nt][hf * 2 + 0] + ci.x + bi0);
                float i1 = sigf(acc[0][mt][nt][hf * 2 + 1] + ci.y + bi1);
                float o0 = sigf(acc[1][mt][nt][hf * 2 + 0] + co.x + bo0);
                float o1 = sigf(acc[1][mt][nt][hf * 2 + 1] + co.y + bo1);
                float u0 = tanhf(acc[2][mt][nt][hf * 2 + 0] + cu.x + bu0);
                float u1 = tanhf(acc[2][mt][nt][hf * 2 + 1] + cu.y + bu1);
                float c0 = i0 * u0, c1 = i1 * u1;
                float h0 = o0 * tanhf(c0), h1 = o1 * tanhf(c1);
                size_t gi = (size_t)(4369 + row) * HID + col;
                *(float2*)(g_C + gi) = make_float2(c0, c1);
                *(float2*)(g_H + gi) = make_float2(h0, h1);
                hlf hh0, ll0, hh1, ll1;
                split1(c0, hh0, ll0); split1(c1, hh1, ll1);
                __half2 vh; vh.x = hh0; vh.y = hh1;
                __half2 vl; vl.x = ll0; vl.y = ll1;
                *(__half2*)(g_Ch + gi) = vh;
                *(__half2*)(g_Cl + gi) = vl;
            }
        }
    }
}

// ---------------------------------------------------------------------------
// Split-fp16 GEMM, CTA 128x128, 512 threads / 16 warps, warp tile 32x32,
// BK=32, 3-stage cp.async. f32 main acc + f16 corr acc.
// N%128==0, K%32==0; M guarded.
// ---------------------------------------------------------------------------
#define TPITCH 80
#define TILE_B (128 * TPITCH)
#define STAGE_B (4 * TILE_B)
#define GSMEM (3 * STAGE_B + 128)

__global__ __launch_bounds__(512)
void gemm_split(const hlf* __restrict__ Ah, const hlf* __restrict__ Al,
                const hlf* __restrict__ Bh, const hlf* __restrict__ Bl,
                float* __restrict__ C, const float* __restrict__ bias,
                int M, int N, int K) {
    extern __shared__ char smem_raw[];
    const uint32_t sbase = (smem_u32(smem_raw) + 127) & ~127u;

    const int tid  = threadIdx.x;
    const int lane = tid & 31;
    const int wid  = tid >> 5;          // 0..15
    const int wm   = wid >> 2;          // 0..3
    const int wn   = wid & 3;           // 0..3
    const int bm   = blockIdx.y * 128;
    const int bn   = blockIdx.x * 128;
    const int NC   = K >> 5;

    const int ag = lane >> 3, ai = lane & 7;
    const int a_row = ai + (ag & 1) * 8;
    const int a_kb  = (ag >> 1) * 16;
    const int b_row = lane & 7;
    const int b_kb  = ((lane >> 3) & 1) * 16;

    float    acc [2][4][4];
    uint32_t corr[2][4][2];
#pragma unroll
    for (int mt = 0; mt < 2; mt++)
#pragma unroll
        for (int nt = 0; nt < 4; nt++) {
#pragma unroll
            for (int j = 0; j < 4; j++) acc[mt][nt][j] = 0.f;
            corr[mt][nt][0] = 0u; corr[mt][nt][1] = 0u;
        }

    auto load_chunk = [&](int c, int s) {
        const uint32_t sb = sbase + s * STAGE_B;
        const int k0 = c << 5;
        int row = tid >> 2, cb = tid & 3;
        int ar = bm + row; if (ar > M - 1) ar = M - 1;
        size_t aoff = (size_t)ar * K + k0 + cb * 8;
        size_t boff = (size_t)(bn + row) * K + k0 + cb * 8;
        uint32_t so = row * TPITCH + cb * 16;
        cp16(sb + so,              Ah + aoff);
        cp16(sb + TILE_B + so,     Al + aoff);
        cp16(sb + 2 * TILE_B + so, Bh + boff);
        cp16(sb + 3 * TILE_B + so, Bl + boff);
        CP_COMMIT();
    };

    load_chunk(0, 0);
    if (NC > 1) load_chunk(1, 1);

    for (int c = 0; c < NC; ++c) {
        if (c + 2 < NC) load_chunk(c + 2, (c + 2) % 3);

        if (c + 2 < NC)      asm volatile("cp.async.wait_group 2;" ::: "memory");
        else if (c + 1 < NC) asm volatile("cp.async.wait_group 1;" ::: "memory");
        else                 asm volatile("cp.async.wait_group 0;" ::: "memory");
        __syncthreads();

        const uint32_t sb  = sbase + (c % 3) * STAGE_B;
        const uint32_t tAh = sb,              tAl = sb + TILE_B;
        const uint32_t tBh = sb + 2 * TILE_B, tBl = sb + 3 * TILE_B;

#pragma unroll
        for (int ks = 0; ks < 2; ++ks) {
            const int kb = ks * 32;
            uint32_t ah[2][4], al[2][4], bhf[4][2], blf[4][2];
#pragma unroll
            for (int mt = 0; mt < 2; ++mt) {
                uint32_t ro = (wm * 32 + mt * 16 + a_row) * TPITCH + a_kb + kb;
                ldsm4(ah[mt], tAh + ro);
                ldsm4(al[mt], tAl + ro);
            }
#pragma unroll
            for (int nt = 0; nt < 4; ++nt) {
                uint32_t ro = (wn * 32 + nt * 8 + b_row) * TPITCH + b_kb + kb;
                ldsm2(bhf[nt], tBh + ro);
                ldsm2(blf[nt], tBl + ro);
            }
#pragma unroll
            for (int mt = 0; mt < 2; ++mt)
#pragma unroll
                for (int nt = 0; nt < 4; ++nt) {
                    mma16816 (acc [mt][nt], ah[mt], bhf[nt]);
                    mma16816h(corr[mt][nt], ah[mt], blf[nt]);
                    mma16816h(corr[mt][nt], al[mt], bhf[nt]);
                }
        }
        __syncthreads();
    }

    const int r0 = lane >> 2;
    const int q2 = (lane & 3) * 2;
#pragma unroll
    for (int mt = 0; mt < 2; ++mt) {
        int row = bm + wm * 32 + mt * 16 + r0;
#pragma unroll
        for (int nt = 0; nt < 4; ++nt) {
            int col = bn + wn * 32 + nt * 8 + q2;
            float bx = 0.f, by = 0.f;
            if (bias) { bx = bias[col]; by = bias[col + 1]; }
            float2 c01 = __half22float2(((__half2*)corr[mt][nt])[0]);
            float2 c23 = __half22float2(((__half2*)corr[mt][nt])[1]);
            if (row < M)
                *(float2*)(C + (size_t)row * N + col) =
                    make_float2(acc[mt][nt][0] + c01.x + bx,
                                acc[mt][nt][1] + c01.y + by);
            if (row + 8 < M)
                *(float2*)(C + (size_t)(row + 8) * N + col) =
                    make_float2(acc[mt][nt][2] + c23.x + bx,
                                acc[mt][nt][3] + c23.y + by);
        }
    }
}

// ---------------------------------------------------------------------------
// Split-fp16 GEMM, CTA 64x64 (small M tail). 128 threads, 4 warps 32x32.
// f32 3-term (time-negligible).
// ---------------------------------------------------------------------------
#define G64_T (64 * TPITCH)
#define G64_STAGE (4 * G64_T)
#define G64_SMEM (3 * G64_STAGE + 128)

__global__ __launch_bounds__(128)
void gemm_split64(const hlf* __restrict__ Ah, const hlf* __restrict__ Al,
                  const hlf* __restrict__ Bh, const hlf* __restrict__ Bl,
                  float* __restrict__ C, const float* __restrict__ bias,
                  int M, int N, int K) {
    extern __shared__ char smem_raw[];
    const uint32_t sbase = (smem_u32(smem_raw) + 127) & ~127u;

    const int tid  = threadIdx.x;
    const int lane = tid & 31;
    const int wid  = tid >> 5;
    const int wm   = wid >> 1;
    const int wn   = wid & 1;
    const int bm   = blockIdx.y * 64;
    const int bn   = blockIdx.x * 64;
    const int NC   = K >> 5;

    const int ag = lane >> 3, ai = lane & 7;
    const int a_row = ai + (ag & 1) * 8;
    const int a_kb  = (ag >> 1) * 16;
    const int b_row = lane & 7;
    const int b_kb  = ((lane >> 3) & 1) * 16;

    float acc[2][4][4];
#pragma unroll
    for (int mt = 0; mt < 2; mt++)
#pragma unroll
        for (int nt = 0; nt < 4; nt++)
#pragma unroll
            for (int j = 0; j < 4; j++) acc[mt][nt][j] = 0.f;

    auto load_chunk = [&](int c, int s) {
        const uint32_t sb = sbase + s * G64_STAGE;
        const int k0 = c << 5;
#pragma unroll
        for (int it = 0; it < 2; ++it) {
            int idx = tid + it * 128;
            int row = idx >> 2, cb = idx & 3;
            int ar = bm + row; if (ar > M - 1) ar = M - 1;
            size_t aoff = (size_t)ar * K + k0 + cb * 8;
            size_t boff = (size_t)(bn + row) * K + k0 + cb * 8;
            uint32_t so = row * TPITCH + cb * 16;
            cp16(sb + so,             Ah + aoff);
            cp16(sb + G64_T + so,     Al + aoff);
            cp16(sb + 2 * G64_T + so, Bh + boff);
            cp16(sb + 3 * G64_T + so, Bl + boff);
        }
        CP_COMMIT();
    };

    load_chunk(0, 0);
    if (NC > 1) load_chunk(1, 1);

    for (int c = 0; c < NC; ++c) {
        if (c + 2 < NC) load_chunk(c + 2, (c + 2) % 3);

        if (c + 2 < NC)      asm volatile("cp.async.wait_group 2;" ::: "memory");
        else if (c + 1 < NC) asm volatile("cp.async.wait_group 1;" ::: "memory");
        else                 asm volatile("cp.async.wait_group 0;" ::: "memory");
        __syncthreads();

        const uint32_t sb  = sbase + (c % 3) * G64_STAGE;
        const uint32_t tAh = sb,             tAl = sb + G64_T;
        const uint32_t tBh = sb + 2 * G64_T, tBl = sb + 3 * G64_T;

#pragma unroll
        for (int ks = 0; ks < 2; ++ks) {
            const int kb = ks * 32;
            uint32_t ah[2][4], al[2][4], bhf[4][2], blf[4][2];
#pragma unroll
            for (int mt = 0; mt < 2; ++mt) {
                uint32_t ro = (wm * 32 + mt * 16 + a_row) * TPITCH + a_kb + kb;
                ldsm4(ah[mt], tAh + ro);
                ldsm4(al[mt], tAl + ro);
            }
#pragma unroll
            for (int nt = 0; nt < 4; ++nt) {
                uint32_t ro = (wn * 32 + nt * 8 + b_row) * TPITCH + b_kb + kb;
                ldsm2(bhf[nt], tBh + ro);
                ldsm2(blf[nt], tBl + ro);
            }
#pragma unroll
            for (int mt = 0; mt < 2; ++mt)
#pragma unroll
                for (int nt = 0; nt < 4; ++nt) {
                    mma16816(acc[mt][nt], ah[mt], bhf[nt]);
                    mma16816(acc[mt][nt], ah[mt], blf[nt]);
                    mma16816(acc[mt][nt], al[mt], bhf[nt]);
                }
        }
        __syncthreads();
    }

    const int r0 = lane >> 2;
    const int q2 = (lane & 3) * 2;
#pragma unroll
    for (int mt = 0; mt < 2; ++mt) {
        int row = bm + wm * 32 + mt * 16 + r0;
#pragma unroll
        for (int nt = 0; nt < 4; ++nt) {
            int col = bn + wn * 32 + nt * 8 + q2;
            float bx = 0.f, by = 0.f;
            if (bias) { bx = bias[col]; by = bias[col + 1]; }
            if (row < M)
                *(float2*)(C + (size_t)row * N + col) =
                    make_float2(acc[mt][nt][0] + bx, acc[mt][nt][1] + by);
            if (row + 8 < M)
                *(float2*)(C + (size_t)(row + 8) * N + col) =
                    make_float2(acc[mt][nt][2] + bx, acc[mt][nt][3] + by);
        }
    }
}

// ---------------------------------------------------------------------------
// Weight packing (fp32 -> split fp16) + biases
// ---------------------------------------------------------------------------
__global__ void pack_weights(const float* __restrict__ wi_w, const float* __restrict__ wi_b,
                             const float* __restrict__ wf_w, const float* __restrict__ wf_b,
                             const float* __restrict__ wo_w, const float* __restrict__ wo_b,
                             const float* __restrict__ wu_w, const float* __restrict__ wu_b) {
    int idx = blockIdx.x * blockDim.x + threadIdx.x;

    if (idx < 2048 * 1024) {
        int r = idx >> 10, k = idx & 1023;
        float v;
        if      (r <  512) v = wi_w[r * 1024 + k];
        else if (r < 1024) v = wo_w[(r -  512) * 1024 + k];
        else if (r < 1536) v = wu_w[(r - 1024) * 1024 + k];
        else               v = (k < 512) ? wf_w[(r - 1536) * 1024 + k] : 0.f;
        split1(v, g_Wnh[idx], g_Wnl[idx]);
    }
    if (idx < 1536 * 512) {
        int r = idx >> 9, k = idx & 511;
        float v;
        if      (r <  512) v = wi_w[r * 1024 + k];
        else if (r < 1024) v = wo_w[(r -  512) * 1024 + k];
        else               v = wu_w[(r - 1024) * 1024 + k];
        split1(v, g_Wlh[idx], g_Wll[idx]);
    }
    if (idx < 512 * 512) {
        int r = idx >> 9, k = idx & 511;
        split1(wf_w[r * 1024 + 512 + k], g_Wfhh[idx], g_Wfhl[idx]);
    }
    if (idx < 1536)
        g_bleaf[idx] = (idx < 512) ? wi_b[idx] : (idx < 1024) ? wo_b[idx - 512] : wu_b[idx - 1024];
    if (idx < 2048)
        g_bnode[idx] = (idx <  512) ? wi_b[idx]
                     : (idx < 1024) ? wo_b[idx -  512]
                     : (idx < 1536) ? wu_b[idx - 1024] : wf_b[idx - 1536];
}

// fp32 -> split fp16, 4 elems/thread
__global__ void split4(const float* __restrict__ src, hlf* __restrict__ h,
                       hlf* __restrict__ l, int n4) {
    int i = blockIdx.x * blockDim.x + threadIdx.x;
    if (i >= n4) return;
    float4 v = ((const float4*)src)[i];
    hlf hh[4], ll[4];
    split1(v.x, hh[0], ll[0]); split1(v.y, hh[1], ll[1]);
    split1(v.z, hh[2], ll[2]); split1(v.w, hh[3], ll[3]);
    ((uint2*)h)[i] = *(uint2*)hh;
    ((uint2*)l)[i] = *(uint2*)ll;
}

// ---------------------------------------------------------------------------
// Elementwise stages (float4 vectorized)
// ---------------------------------------------------------------------------
__global__ void concat_xh4(const float* __restrict__ x, int off_d, int off_c, int n) {
    int idx = blockIdx.x * blockDim.x + threadIdx.x;
    if (idx >= n * 256) return;
    int r = idx >> 8, c4 = (idx & 255) * 4;
    float4 v;
    if (c4 < 512) {
        v = *(const float4*)(x + (size_t)(off_d + r) * IN_DIM + c4);
    } else {
        int hc = c4 - 512;
        size_t base = (size_t)(off_c + r * 16) * HID + hc;
        v = make_float4(0.f, 0.f, 0.f, 0.f);
#pragma unroll
        for (int k = 0; k < 16; k++) {
            float4 t = *(const float4*)(g_H + base + k * HID);
            v.x += t.x; v.y += t.y; v.z += t.z; v.w += t.w;
        }
    }
    hlf hh[4], ll[4];
    split1(v.x, hh[0], ll[0]); split1(v.y, hh[1], ll[1]);
    split1(v.z, hh[2], ll[2]); split1(v.w, hh[3], ll[3]);
    size_t o = (size_t)r * 1024 + c4;
    *(uint2*)(g_XHh + o) = *(uint2*)hh;
    *(uint2*)(g_XHl + o) = *(uint2*)ll;
}

__global__ void node_epilogue4(int off_d, int off_c, int n) {
    int idx = blockIdx.x * blockDim.x + threadIdx.x;
    if (idx >= n * 128) return;
    int r = idx >> 7, h4 = (idx & 127) * 4;
    const float* g = g_G + (size_t)r * 2048;
    float4 gi = *(const float4*)(g + h4);
    float4 go = *(const float4*)(g + 512 + h4);
    float4 gu = *(const float4*)(g + 1024 + h4);
    float4 gf = *(const float4*)(g + 1536 + h4);
    float a0 = sigf(gi.x) * tanhf(gu.x);
    float a1 = sigf(gi.y) * tanhf(gu.y);
    float a2 = sigf(gi.z) * tanhf(gu.z);
    float a3 = sigf(gi.w) * tanhf(gu.w);
    size_t cb = (size_t)(off_c + r * 16) * HID + h4;
#pragma unroll
    for (int k = 0; k < 16; k++) {
        float4 fh = *(const float4*)(g_FH + cb + k * HID);
        float4 cc = *(const float4*)(g_C  + cb + k * HID);
        a0 += sigf(gf.x + fh.x) * cc.x;
        a1 += sigf(gf.y + fh.y) * cc.y;
        a2 += sigf(gf.z + fh.z) * cc.z;
        a3 += sigf(gf.w + fh.w) * cc.w;
    }
    size_t gidx = (size_t)(off_d + r) * HID + h4;
    *(float4*)(g_C + gidx) = make_float4(a0, a1, a2, a3);
    float4 hv = make_float4(sigf(go.x) * tanhf(a0), sigf(go.y) * tanhf(a1),
                            sigf(go.z) * tanhf(a2), sigf(go.w) * tanhf(a3));
    *(float4*)(g_H + gidx) = hv;
    hlf hh[4], ll[4];
    split1(a0, hh[0], ll[0]); split1(a1, hh[1], ll[1]);
    split1(a2, hh[2], ll[2]); split1(a3, hh[3], ll[3]);
    *(uint2*)(g_Ch + gidx) = *(uint2*)hh;
    *(uint2*)(g_Cl + gidx) = *(uint2*)ll;
}

__global__ void writeout(float* __restrict__ out) {
    int idx = blockIdx.x * blockDim.x + threadIdx.x;
    if (idx < 512)       out[idx] = g_H[idx];
    else if (idx < 1024) out[idx] = g_C[idx - 512];
}

// ---------------------------------------------------------------------------
// Launch
// ---------------------------------------------------------------------------
static void launch_gemm(const hlf* Ah, const hlf* Al, const hlf* Bh, const hlf* Bl,
                        float* C, const float* bias, int M, int N, int K) {
    if (M >= 1024) {
        dim3 grid(N / 128, (M + 127) / 128);
        gemm_split<<<grid, 512, GSMEM>>>(Ah, Al, Bh, Bl, C, bias, M, N, K);
    } else {
        dim3 grid(N / 64, (M + 63) / 64);
        gemm_split64<<<grid, 128, G64_SMEM>>>(Ah, Al, Bh, Bl, C, bias, M, N, K);
    }
}

extern "C" void kernel_launch(void* const* d_in, const int* in_sizes, int n_in,
                              void* d_out, int out_size) {
    const float* x    = (const float*)d_in[0];
    const float* wi_w = (const float*)d_in[1];
    const float* wi_b = (const float*)d_in[2];
    const float* wf_w = (const float*)d_in[3];
    const float* wf_b = (const float*)d_in[4];
    const float* wo_w = (const float*)d_in[5];
    const float* wo_b = (const float*)d_in[6];
    const float* wu_w = (const float*)d_in[7];
    const float* wu_b = (const float*)d_in[8];
    float* out = (float*)d_out;

    cudaFuncSetAttribute(gemm_split,   cudaFuncAttributeMaxDynamicSharedMemorySize, GSMEM);
    cudaFuncSetAttribute(gemm_split64, cudaFuncAttributeMaxDynamicSharedMemorySize, G64_SMEM);
    cudaFuncSetAttribute(leaf_fused,   cudaFuncAttributeMaxDynamicSharedMemorySize, LF_SMEM);

    float *pC, *pFH, *pG, *pbn;
    hlf *pXh, *pXl, *pCh, *pCl, *pXHh, *pXHl, *pWnh, *pWnl, *pWfhh, *pWfhl;
    cudaGetSymbolAddress((void**)&pC,    g_C);
    cudaGetSymbolAddress((void**)&pFH,   g_FH);
    cudaGetSymbolAddress((void**)&pG,    g_G);
    cudaGetSymbolAddress((void**)&pbn,   g_bnode);
    cudaGetSymbolAddress((void**)&pXh,   g_Xh);
    cudaGetSymbolAddress((void**)&pXl,   g_Xl);
    cudaGetSymbolAddress((void**)&pCh,   g_Ch);
    cudaGetSymbolAddress((void**)&pCl,   g_Cl);
    cudaGetSymbolAddress((void**)&pXHh,  g_XHh);
    cudaGetSymbolAddress((void**)&pXHl,  g_XHl);
    cudaGetSymbolAddress((void**)&pWnh,  g_Wnh);
    cudaGetSymbolAddress((void**)&pWnl,  g_Wnl);
    cudaGetSymbolAddress((void**)&pWfhh, g_Wfhh);
    cudaGetSymbolAddress((void**)&pWfhl, g_Wfhl);

    static const int offs[6]  = {0, 1, 17, 273, 4369, 69905};
    static const int sizes[5] = {1, 16, 256, 4096, 65536};

    // 1) weights -> split fp16
    pack_weights<<<(2048 * 1024 + 255) / 256, 256>>>(wi_w, wi_b, wf_w, wf_b,
                                                     wo_w, wo_b, wu_w, wu_b);
    // 2) leaf x -> split fp16
    split4<<<(NLEAF * IN_DIM / 4 + 255) / 256, 256>>>(x + (size_t)offs[4] * IN_DIM,
                                                      pXh, pXl, NLEAF * IN_DIM / 4);
    // 3) fused leaf gates (writes C,H,Ch,Cl), then FH GEMM
    {
        dim3 grid(HID / 64, NLEAF / 128);
        leaf_fused<<<grid, 512, LF_SMEM>>>(pXh, pXl);
    }
    launch_gemm(pCh + (size_t)offs[4] * HID, pCl + (size_t)offs[4] * HID,
                pWfhh, pWfhl, pFH + (size_t)offs[4] * HID, nullptr, NLEAF, 512, 512);

    // 4) internal levels, bottom-up
    for (int d = 3; d >= 0; d--) {
        int n = sizes[d];
        concat_xh4<<<(n * 256 + 255) / 256, 256>>>(x, offs[d], offs[d + 1], n);
        launch_gemm(pXHh, pXHl, pWnh, pWnl, pG, pbn, n, 2048, 1024);
        node_epilogue4<<<(n * 128 + 255) / 256, 256>>>(offs[d], offs[d + 1], n);
        if (d > 0)
            launch_gemm(pCh + (size_t)offs[d] * HID, pCl + (size_t)offs[d] * HID,
                        pWfhh, pWfhl, pFH + (size_t)offs[d] * HID, nullptr, n, 512, 512);
    }

    // 5) output: H[0] then C[0]
    writeout<<<4, 256>>>(out);
}

// round 8
// speedup vs baseline: 1.3874x; 1.3874x over previous
#include <cuda_runtime.h>
#include <cuda_fp16.h>
#include <math.h>
#include <stdint.h>

// ---------------------------------------------------------------------------
// CSTreeLSTM on GB300: 2-term split-fp16 HMMA GEMMs.
// C = (Ah+Al) @ Bh^T  (activations split hi/lo fp16; weights rounded fp16).
// Dropped terms: A*Bl ~2^-12 (weight rounding), AlBl ~2^-22.
// Tree: 16-ary, depth 4, IN=HID=512. Levels 1,16,256,4096,65536
// (offsets 0,1,17,273,4369; total 69905).
// ---------------------------------------------------------------------------

#define IN_DIM 512
#define HID    512
#define NLEAF  65536
#define NTOT   69905

typedef __half hlf;

// ------------------------------ device scratch ------------------------------
__device__ __align__(128) float g_C [NTOT * HID];
__device__ __align__(128) float g_H [NTOT * HID];
__device__ __align__(128) float g_FH[NTOT * HID];
__device__ __align__(128) float g_G [4096 * 2048];   // node-level gates only

__device__ __align__(128) hlf g_Xh [NLEAF * IN_DIM];
__device__ __align__(128) hlf g_Xl [NLEAF * IN_DIM];
__device__ __align__(128) hlf g_Ch [NTOT * HID];
__device__ __align__(128) hlf g_Cl [NTOT * HID];
__device__ __align__(128) hlf g_XHh[4096 * 1024];
__device__ __align__(128) hlf g_XHl[4096 * 1024];

__device__ __align__(128) hlf g_Wnh[2048 * 1024];
__device__ __align__(128) hlf g_Wlh[1536 * 512];
__device__ __align__(128) hlf g_Wfhh[512 * 512];
__device__ float g_bleaf[1536];
__device__ float g_bnode[2048];

__device__ __forceinline__ float sigf(float x) { return 1.f / (1.f + expf(-x)); }

__device__ __forceinline__ void split1(float v, hlf& h, hlf& l) {
    h = __float2half_rn(v);
    l = __float2half_rn(v - __half2float(h));
}

// ------------------------------ PTX helpers ---------------------------------
__device__ __forceinline__ uint32_t smem_u32(const void* p) {
    uint32_t a;
    asm("{ .reg .u64 t; cvta.to.shared.u64 t, %1; cvt.u32.u64 %0, t; }" : "=r"(a) : "l"(p));
    return a;
}

__device__ __forceinline__ void cp16(uint32_t dst, const void* src) {
    asm volatile("cp.async.cg.shared.global [%0], [%1], 16;" :: "r"(dst), "l"(src));
}
#define CP_COMMIT() asm volatile("cp.async.commit_group;" ::: "memory")

__device__ __forceinline__ void ldsm4(uint32_t* r, uint32_t addr) {
    asm volatile("ldmatrix.sync.aligned.m8n8.x4.shared.b16 {%0,%1,%2,%3}, [%4];"
                 : "=r"(r[0]), "=r"(r[1]), "=r"(r[2]), "=r"(r[3]) : "r"(addr));
}
__device__ __forceinline__ void mma16816(float* d, const uint32_t* a, const uint32_t* b) {
    asm volatile(
        "mma.sync.aligned.m16n8k16.row.col.f32.f16.f16.f32 "
        "{%0,%1,%2,%3}, {%4,%5,%6,%7}, {%8,%9}, {%0,%1,%2,%3};"
        : "+f"(d[0]), "+f"(d[1]), "+f"(d[2]), "+f"(d[3])
        : "r"(a[0]), "r"(a[1]), "r"(a[2]), "r"(a[3]), "r"(b[0]), "r"(b[1]));
}

// ---------------------------------------------------------------------------
// Fused leaf kernel. CTA tile: 128(M) x 64(h), 3 gates. 512 threads,
// 16 warps, warp tile 32x16 per gate, BK=32, 3 stages. M%128==0, K=512.
// 2-term: Ah,Al tiles + Bh tile per gate.
// ---------------------------------------------------------------------------
#define LF_PITCH 80
#define LF_AT (128 * LF_PITCH)                 // 10240
#define LF_BT (64 * LF_PITCH)                  // 5120
#define LF_STAGE (2 * LF_AT + 3 * LF_BT)       // 35840
#define LF_SMEM (3 * LF_STAGE + 128)

__global__ __launch_bounds__(512)
void leaf_fused(const hlf* __restrict__ Ah, const hlf* __restrict__ Al) {
    extern __shared__ char smem_raw[];
    const uint32_t sbase = (smem_u32(smem_raw) + 127) & ~127u;

    const int tid  = threadIdx.x;
    const int lane = tid & 31;
    const int wid  = tid >> 5;
    const int wm   = wid >> 2;
    const int wn   = wid & 3;
    const int bm   = blockIdx.y * 128;
    const int bh   = blockIdx.x * 64;
    const int K    = 512;
    const int NC   = 16;

    const int ag = lane >> 3, ai = lane & 7;
    const int a_row = ai + (ag & 1) * 8;
    const int a_kb  = (ag >> 1) * 16;
    // x4 B pairing: lanes 0-15 -> nt block, lanes 16-31 -> nt+1 block
    const int b_row2 = (lane & 7) + ((lane >> 4) << 3);
    const int b_kb   = ((lane >> 3) & 1) * 16;

    float acc[3][2][2][4];
#pragma unroll
    for (int g = 0; g < 3; g++)
#pragma unroll
        for (int mt = 0; mt < 2; mt++)
#pragma unroll
            for (int nt = 0; nt < 2; nt++)
#pragma unroll
                for (int j = 0; j < 4; j++) acc[g][mt][nt][j] = 0.f;

    auto load_chunk = [&](int c, int s) {
        const uint32_t sb = sbase + s * LF_STAGE;
        const int k0 = c << 5;
        {   // A tiles: 512 positions each, 1/thread
            int row = tid >> 2, cb = tid & 3;
            size_t aoff = (size_t)(bm + row) * K + k0 + cb * 8;
            uint32_t so = row * LF_PITCH + cb * 16;
            cp16(sb + so,         Ah + aoff);
            cp16(sb + LF_AT + so, Al + aoff);
        }
        // B (h only): 3 gates x 256 positions = 768
#pragma unroll
        for (int i = 0; i < 2; ++i) {
            int p = tid + i * 512;
            if (p < 768) {
                int g = p >> 8, pp = p & 255;
                int row = pp >> 2, cb = pp & 3;
                size_t woff = (size_t)(g * 512 + bh + row) * 512 + k0 + cb * 8;
                uint32_t so = row * LF_PITCH + cb * 16;
                cp16(sb + 2 * LF_AT + g * LF_BT + so, g_Wlh + woff);
            }
        }
        CP_COMMIT();
    };

    load_chunk(0, 0);
    load_chunk(1, 1);

    for (int c = 0; c < NC; ++c) {
        if (c + 2 < NC) load_chunk(c + 2, (c + 2) % 3);

        if (c + 2 < NC)      asm volatile("cp.async.wait_group 2;" ::: "memory");
        else if (c + 1 < NC) asm volatile("cp.async.wait_group 1;" ::: "memory");
        else                 asm volatile("cp.async.wait_group 0;" ::: "memory");
        __syncthreads();

        const uint32_t sb = sbase + (c % 3) * LF_STAGE;

#pragma unroll
        for (int ks = 0; ks < 2; ++ks) {
            const int kb = ks * 32;
            uint32_t ah[2][4], al[2][4];
#pragma unroll
            for (int mt = 0; mt < 2; ++mt) {
                uint32_t ro = (wm * 32 + mt * 16 + a_row) * LF_PITCH + a_kb + kb;
                ldsm4(ah[mt], sb + ro);
                ldsm4(al[mt], sb + LF_AT + ro);
            }
            uint32_t bg[3][4];   // per gate: [nt0 b0,b1, nt1 b0,b1]
#pragma unroll
            for (int g = 0; g < 3; ++g) {
                uint32_t ro = (wn * 16 + b_row2) * LF_PITCH + b_kb + kb;
                ldsm4(bg[g], sb + 2 * LF_AT + g * LF_BT + ro);
            }
#pragma unroll
            for (int g = 0; g < 3; ++g)
#pragma unroll
                for (int mt = 0; mt < 2; ++mt)
#pragma unroll
                    for (int nt = 0; nt < 2; ++nt) {
                        mma16816(acc[g][mt][nt], ah[mt], &bg[g][nt * 2]);
                        mma16816(acc[g][mt][nt], al[mt], &bg[g][nt * 2]);
                    }
        }
        __syncthreads();
    }

    const int r0 = lane >> 2;
    const int q2 = (lane & 3) * 2;
#pragma unroll
    for (int mt = 0; mt < 2; ++mt) {
#pragma unroll
        for (int nt = 0; nt < 2; ++nt) {
            int col = bh + wn * 16 + nt * 8 + q2;
            float bi0 = g_bleaf[col],        bi1 = g_bleaf[col + 1];
            float bo0 = g_bleaf[512 + col],  bo1 = g_bleaf[512 + col + 1];
            float bu0 = g_bleaf[1024 + col], bu1 = g_bleaf[1024 + col + 1];
#pragma unroll
            for (int hf = 0; hf < 2; ++hf) {
                int row = bm + wm * 32 + mt * 16 + r0 + hf * 8;
                float i0 = sigf(acc[0][mt][nt][hf * 2 + 0] + bi0);
                float i1 = sigf(acc[0][mt][nt][hf * 2 + 1] + bi1);
                float o0 = sigf(acc[1][mt][nt][hf * 2 + 0] + bo0);
                float o1 = sigf(acc[1][mt][nt][hf * 2 + 1] + bo1);
                float u0 = tanhf(acc[2][mt][nt][hf * 2 + 0] + bu0);
                float u1 = tanhf(acc[2][mt][nt][hf * 2 + 1] + bu1);
                float c0 = i0 * u0, c1 = i1 * u1;
                float h0 = o0 * tanhf(c0), h1 = o1 * tanhf(c1);
                size_t gi = (size_t)(4369 + row) * HID + col;
                *(float2*)(g_C + gi) = make_float2(c0, c1);
                *(float2*)(g_H + gi) = make_float2(h0, h1);
                hlf hh0, ll0, hh1, ll1;
                split1(c0, hh0, ll0); split1(c1, hh1, ll1);
                __half2 vh; vh.x = hh0; vh.y = hh1;
                __half2 vl; vl.x = ll0; vl.y = ll1;
                *(__half2*)(g_Ch + gi) = vh;
                *(__half2*)(g_Cl + gi) = vl;
            }
        }
    }
}

// ---------------------------------------------------------------------------
// 2-term split GEMM, CTA 128(M) x 256(N), 512 threads / 16 warps,
// warp tile 32x64, BK=32, 3-stage cp.async. N%256==0, K%32==0; M guarded.
// ---------------------------------------------------------------------------
#define TPITCH 80
#define AT_B (128 * TPITCH)            // 10240
#define BT_B (256 * TPITCH)            // 20480
#define STAGE_B (2 * AT_B + BT_B)      // 40960
#define GSMEM (3 * STAGE_B + 128)

__global__ __launch_bounds__(512)
void gemm_split(const hlf* __restrict__ Ah, const hlf* __restrict__ Al,
                const hlf* __restrict__ Bh,
                float* __restrict__ C, const float* __restrict__ bias,
                int M, int N, int K) {
    extern __shared__ char smem_raw[];
    const uint32_t sbase = (smem_u32(smem_raw) + 127) & ~127u;

    const int tid  = threadIdx.x;
    const int lane = tid & 31;
    const int wid  = tid >> 5;          // 0..15
    const int wm   = wid >> 2;          // 0..3 (M slices of 32)
    const int wn   = wid & 3;           // 0..3 (N slices of 64)
    const int bm   = blockIdx.y * 128;
    const int bn   = blockIdx.x * 256;
    const int NC   = K >> 5;

    const int ag = lane >> 3, ai = lane & 7;
    const int a_row = ai + (ag & 1) * 8;
    const int a_kb  = (ag >> 1) * 16;
    const int b_row2 = (lane & 7) + ((lane >> 4) << 3);
    const int b_kb   = ((lane >> 3) & 1) * 16;

    float acc[2][8][4];
#pragma unroll
    for (int mt = 0; mt < 2; mt++)
#pragma unroll
        for (int nt = 0; nt < 8; nt++)
#pragma unroll
            for (int j = 0; j < 4; j++) acc[mt][nt][j] = 0.f;

    auto load_chunk = [&](int c, int s) {
        const uint32_t sb = sbase + s * STAGE_B;
        const int k0 = c << 5;
        {   // A: 512 positions, 1/thread per tile
            int row = tid >> 2, cb = tid & 3;
            int ar = bm + row; if (ar > M - 1) ar = M - 1;
            size_t aoff = (size_t)ar * K + k0 + cb * 8;
            uint32_t so = row * TPITCH + cb * 16;
            cp16(sb + so,        Ah + aoff);
            cp16(sb + AT_B + so, Al + aoff);
        }
#pragma unroll
        for (int i = 0; i < 2; ++i) {   // B: 1024 positions, 2/thread
            int p = tid + i * 512;
            int row = p >> 2, cb = p & 3;
            size_t boff = (size_t)(bn + row) * K + k0 + cb * 8;
            uint32_t so = row * TPITCH + cb * 16;
            cp16(sb + 2 * AT_B + so, Bh + boff);
        }
        CP_COMMIT();
    };

    load_chunk(0, 0);
    if (NC > 1) load_chunk(1, 1);

    for (int c = 0; c < NC; ++c) {
        if (c + 2 < NC) load_chunk(c + 2, (c + 2) % 3);

        if (c + 2 < NC)      asm volatile("cp.async.wait_group 2;" ::: "memory");
        else if (c + 1 < NC) asm volatile("cp.async.wait_group 1;" ::: "memory");
        else                 asm volatile("cp.async.wait_group 0;" ::: "memory");
        __syncthreads();

        const uint32_t sb  = sbase + (c % 3) * STAGE_B;
        const uint32_t tAh = sb, tAl = sb + AT_B, tBh = sb + 2 * AT_B;

#pragma unroll
        for (int ks = 0; ks < 2; ++ks) {
            const int kb = ks * 32;
            uint32_t ah[2][4], al[2][4], bh[8][2];
#pragma unroll
            for (int mt = 0; mt < 2; ++mt) {
                uint32_t ro = (wm * 32 + mt * 16 + a_row) * TPITCH + a_kb + kb;
                ldsm4(ah[mt], tAh + ro);
                ldsm4(al[mt], tAl + ro);
            }
#pragma unroll
            for (int nt2 = 0; nt2 < 8; nt2 += 2) {
                uint32_t ro = (wn * 64 + nt2 * 8 + b_row2) * TPITCH + b_kb + kb;
                ldsm4(&bh[nt2][0], tBh + ro);   // fills bh[nt2][0..1], bh[nt2+1][0..1]
            }
#pragma unroll
            for (int mt = 0; mt < 2; ++mt)
#pragma unroll
                for (int nt = 0; nt < 8; ++nt) {
                    mma16816(acc[mt][nt], ah[mt], bh[nt]);
                    mma16816(acc[mt][nt], al[mt], bh[nt]);
                }
        }
        __syncthreads();
    }

    const int r0 = lane >> 2;
    const int q2 = (lane & 3) * 2;
#pragma unroll
    for (int mt = 0; mt < 2; ++mt) {
        int row = bm + wm * 32 + mt * 16 + r0;
#pragma unroll
        for (int nt = 0; nt < 8; ++nt) {
            int col = bn + wn * 64 + nt * 8 + q2;
            float bx = 0.f, by = 0.f;
            if (bias) { bx = bias[col]; by = bias[col + 1]; }
            if (row < M)
                *(float2*)(C + (size_t)row * N + col) =
                    make_float2(acc[mt][nt][0] + bx, acc[mt][nt][1] + by);
            if (row + 8 < M)
                *(float2*)(C + (size_t)(row + 8) * N + col) =
                    make_float2(acc[mt][nt][2] + bx, acc[mt][nt][3] + by);
        }
    }
}

// ---------------------------------------------------------------------------
// 2-term split GEMM, CTA 64x64 (small M tail). 128 threads, 4 warps 32x32.
// ---------------------------------------------------------------------------
#define G64_T (64 * TPITCH)
#define G64_STAGE (3 * G64_T)
#define G64_SMEM (3 * G64_STAGE + 128)

__global__ __launch_bounds__(128)
void gemm_split64(const hlf* __restrict__ Ah, const hlf* __restrict__ Al,
                  const hlf* __restrict__ Bh,
                  float* __restrict__ C, const float* __restrict__ bias,
                  int M, int N, int K) {
    extern __shared__ char smem_raw[];
    const uint32_t sbase = (smem_u32(smem_raw) + 127) & ~127u;

    const int tid  = threadIdx.x;
    const int lane = tid & 31;
    const int wid  = tid >> 5;
    const int wm   = wid >> 1;
    const int wn   = wid & 1;
    const int bm   = blockIdx.y * 64;
    const int bn   = blockIdx.x * 64;
    const int NC   = K >> 5;

    const int ag = lane >> 3, ai = lane & 7;
    const int a_row = ai + (ag & 1) * 8;
    const int a_kb  = (ag >> 1) * 16;
    const int b_row2 = (lane & 7) + ((lane >> 4) << 3);
    const int b_kb   = ((lane >> 3) & 1) * 16;

    float acc[2][4][4];
#pragma unroll
    for (int mt = 0; mt < 2; mt++)
#pragma unroll
        for (int nt = 0; nt < 4; nt++)
#pragma unroll
            for (int j = 0; j < 4; j++) acc[mt][nt][j] = 0.f;

    auto load_chunk = [&](int c, int s) {
        const uint32_t sb = sbase + s * G64_STAGE;
        const int k0 = c << 5;
#pragma unroll
        for (int it = 0; it < 2; ++it) {
            int idx = tid + it * 128;
            int row = idx >> 2, cb = idx & 3;
            int ar = bm + row; if (ar > M - 1) ar = M - 1;
            size_t aoff = (size_t)ar * K + k0 + cb * 8;
            size_t boff = (size_t)(bn + row) * K + k0 + cb * 8;
            uint32_t so = row * TPITCH + cb * 16;
            cp16(sb + so,             Ah + aoff);
            cp16(sb + G64_T + so,     Al + aoff);
            cp16(sb + 2 * G64_T + so, Bh + boff);
        }
        CP_COMMIT();
    };

    load_chunk(0, 0);
    if (NC > 1) load_chunk(1, 1);

    for (int c = 0; c < NC; ++c) {
        if (c + 2 < NC) load_chunk(c + 2, (c + 2) % 3);

        if (c + 2 < NC)      asm volatile("cp.async.wait_group 2;" ::: "memory");
        else if (c + 1 < NC) asm volatile("cp.async.wait_group 1;" ::: "memory");
        else                 asm volatile("cp.async.wait_group 0;" ::: "memory");
        __syncthreads();

        const uint32_t sb  = sbase + (c % 3) * G64_STAGE;
        const uint32_t tAh = sb, tAl = sb + G64_T, tBh = sb + 2 * G64_T;

#pragma unroll
        for (int ks = 0; ks < 2; ++ks) {
            const int kb = ks * 32;
            uint32_t ah[2][4], al[2][4], bh[4][2];
#pragma unroll
            for (int mt = 0; mt < 2; ++mt) {
                uint32_t ro = (wm * 32 + mt * 16 + a_row) * TPITCH + a_kb + kb;
                ldsm4(ah[mt], tAh + ro);
                ldsm4(al[mt], tAl + ro);
            }
#pragma unroll
            for (int nt2 = 0; nt2 < 4; nt2 += 2) {
                uint32_t ro = (wn * 32 + nt2 * 8 + b_row2) * TPITCH + b_kb + kb;
                ldsm4(&bh[nt2][0], tBh + ro);
            }
#pragma unroll
            for (int mt = 0; mt < 2; ++mt)
#pragma unroll
                for (int nt = 0; nt < 4; ++nt) {
                    mma16816(acc[mt][nt], ah[mt], bh[nt]);
                    mma16816(acc[mt][nt], al[mt], bh[nt]);
                }
        }
        __syncthreads();
    }

    const int r0 = lane >> 2;
    const int q2 = (lane & 3) * 2;
#pragma unroll
    for (int mt = 0; mt < 2; ++mt) {
        int row = bm + wm * 32 + mt * 16 + r0;
#pragma unroll
        for (int nt = 0; nt < 4; ++nt) {
            int col = bn + wn * 32 + nt * 8 + q2;
            float bx = 0.f, by = 0.f;
            if (bias) { bx = bias[col]; by = bias[col + 1]; }
            if (row < M)
                *(float2*)(C + (size_t)row * N + col) =
                    make_float2(acc[mt][nt][0] + bx, acc[mt][nt][1] + by);
            if (row + 8 < M)
                *(float2*)(C + (size_t)(row + 8) * N + col) =
                    make_float2(acc[mt][nt][2] + bx, acc[mt][nt][3] + by);
        }
    }
}

// ---------------------------------------------------------------------------
// Weight packing (fp32 -> fp16, h only) + biases
// ---------------------------------------------------------------------------
__global__ void pack_weights(const float* __restrict__ wi_w, const float* __restrict__ wi_b,
                             const float* __restrict__ wf_w, const float* __restrict__ wf_b,
                             const float* __restrict__ wo_w, const float* __restrict__ wo_b,
                             const float* __restrict__ wu_w, const float* __restrict__ wu_b) {
    int idx = blockIdx.x * blockDim.x + threadIdx.x;

    if (idx < 2048 * 1024) {
        int r = idx >> 10, k = idx & 1023;
        float v;
        if      (r <  512) v = wi_w[r * 1024 + k];
        else if (r < 1024) v = wo_w[(r -  512) * 1024 + k];
        else if (r < 1536) v = wu_w[(r - 1024) * 1024 + k];
        else               v = (k < 512) ? wf_w[(r - 1536) * 1024 + k] : 0.f;
        g_Wnh[idx] = __float2half_rn(v);
    }
    if (idx < 1536 * 512) {
        int r = idx >> 9, k = idx & 511;
        float v;
        if      (r <  512) v = wi_w[r * 1024 + k];
        else if (r < 1024) v = wo_w[(r -  512) * 1024 + k];
        else               v = wu_w[(r - 1024) * 1024 + k];
        g_Wlh[idx] = __float2half_rn(v);
    }
    if (idx < 512 * 512) {
        int r = idx >> 9, k = idx & 511;
        g_Wfhh[idx] = __float2half_rn(wf_w[r * 1024 + 512 + k]);
    }
    if (idx < 1536)
        g_bleaf[idx] = (idx < 512) ? wi_b[idx] : (idx < 1024) ? wo_b[idx - 512] : wu_b[idx - 1024];
    if (idx < 2048)
        g_bnode[idx] = (idx <  512) ? wi_b[idx]
                     : (idx < 1024) ? wo_b[idx -  512]
                     : (idx < 1536) ? wu_b[idx - 1024] : wf_b[idx - 1536];
}

// fp32 -> split fp16, 4 elems/thread
__global__ void split4(const float* __restrict__ src, hlf* __restrict__ h,
                       hlf* __restrict__ l, int n4) {
    int i = blockIdx.x * blockDim.x + threadIdx.x;
    if (i >= n4) return;
    float4 v = ((const float4*)src)[i];
    hlf hh[4], ll[4];
    split1(v.x, hh[0], ll[0]); split1(v.y, hh[1], ll[1]);
    split1(v.z, hh[2], ll[2]); split1(v.w, hh[3], ll[3]);
    ((uint2*)h)[i] = *(uint2*)hh;
    ((uint2*)l)[i] = *(uint2*)ll;
}

// ---------------------------------------------------------------------------
// Elementwise stages (float4 vectorized)
// ---------------------------------------------------------------------------
__global__ void concat_xh4(const float* __restrict__ x, int off_d, int off_c, int n) {
    int idx = blockIdx.x * blockDim.x + threadIdx.x;
    if (idx >= n * 256) return;
    int r = idx >> 8, c4 = (idx & 255) * 4;
    float4 v;
    if (c4 < 512) {
        v = *(const float4*)(x + (size_t)(off_d + r) * IN_DIM + c4);
    } else {
        int hc = c4 - 512;
        size_t base = (size_t)(off_c + r * 16) * HID + hc;
        v = make_float4(0.f, 0.f, 0.f, 0.f);
#pragma unroll
        for (int k = 0; k < 16; k++) {
            float4 t = *(const float4*)(g_H + base + k * HID);
            v.x += t.x; v.y += t.y; v.z += t.z; v.w += t.w;
        }
    }
    hlf hh[4], ll[4];
    split1(v.x, hh[0], ll[0]); split1(v.y, hh[1], ll[1]);
    split1(v.z, hh[2], ll[2]); split1(v.w, hh[3], ll[3]);
    size_t o = (size_t)r * 1024 + c4;
    *(uint2*)(g_XHh + o) = *(uint2*)hh;
    *(uint2*)(g_XHl + o) = *(uint2*)ll;
}

__global__ void node_epilogue4(int off_d, int off_c, int n) {
    int idx = blockIdx.x * blockDim.x + threadIdx.x;
    if (idx >= n * 128) return;
    int r = idx >> 7, h4 = (idx & 127) * 4;
    const float* g = g_G + (size_t)r * 2048;
    float4 gi = *(const float4*)(g + h4);
    float4 go = *(const float4*)(g + 512 + h4);
    float4 gu = *(const float4*)(g + 1024 + h4);
    float4 gf = *(const float4*)(g + 1536 + h4);
    float a0 = sigf(gi.x) * tanhf(gu.x);
    float a1 = sigf(gi.y) * tanhf(gu.y);
    float a2 = sigf(gi.z) * tanhf(gu.z);
    float a3 = sigf(gi.w) * tanhf(gu.w);
    size_t cb = (size_t)(off_c + r * 16) * HID + h4;
#pragma unroll
    for (int k = 0; k < 16; k++) {
        float4 fh = *(const float4*)(g_FH + cb + k * HID);
        float4 cc = *(const float4*)(g_C  + cb + k * HID);
        a0 += sigf(gf.x + fh.x) * cc.x;
        a1 += sigf(gf.y + fh.y) * cc.y;
        a2 += sigf(gf.z + fh.z) * cc.z;
        a3 += sigf(gf.w + fh.w) * cc.w;
    }
    size_t gidx = (size_t)(off_d + r) * HID + h4;
    *(float4*)(g_C + gidx) = make_float4(a0, a1, a2, a3);
    float4 hv = make_float4(sigf(go.x) * tanhf(a0), sigf(go.y) * tanhf(a1),
                            sigf(go.z) * tanhf(a2), sigf(go.w) * tanhf(a3));
    *(float4*)(g_H + gidx) = hv;
    hlf hh[4], ll[4];
    split1(a0, hh[0], ll[0]); split1(a1, hh[1], ll[1]);
    split1(a2, hh[2], ll[2]); split1(a3, hh[3], ll[3]);
    *(uint2*)(g_Ch + gidx) = *(uint2*)hh;
    *(uint2*)(g_Cl + gidx) = *(uint2*)ll;
}

__global__ void writeout(float* __restrict__ out) {
    int idx = blockIdx.x * blockDim.x + threadIdx.x;
    if (idx < 512)       out[idx] = g_H[idx];
    else if (idx < 1024) out[idx] = g_C[idx - 512];
}

// ---------------------------------------------------------------------------
// Launch
// ---------------------------------------------------------------------------
static void launch_gemm(const hlf* Ah, const hlf* Al, const hlf* Bh,
                        float* C, const float* bias, int M, int N, int K) {
    if (M >= 1024) {
        dim3 grid(N / 256, (M + 127) / 128);
        gemm_split<<<grid, 512, GSMEM>>>(Ah, Al, Bh, C, bias, M, N, K);
    } else {
        dim3 grid(N / 64, (M + 63) / 64);
        gemm_split64<<<grid, 128, G64_SMEM>>>(Ah, Al, Bh, C, bias, M, N, K);
    }
}

extern "C" void kernel_launch(void* const* d_in, const int* in_sizes, int n_in,
                              void* d_out, int out_size) {
    const float* x    = (const float*)d_in[0];
    const float* wi_w = (const float*)d_in[1];
    const float* wi_b = (const float*)d_in[2];
    const float* wf_w = (const float*)d_in[3];
    const float* wf_b = (const float*)d_in[4];
    const float* wo_w = (const float*)d_in[5];
    const float* wo_b = (const float*)d_in[6];
    const float* wu_w = (const float*)d_in[7];
    const float* wu_b = (const float*)d_in[8];
    float* out = (float*)d_out;

    cudaFuncSetAttribute(gemm_split,   cudaFuncAttributeMaxDynamicSharedMemorySize, GSMEM);
    cudaFuncSetAttribute(gemm_split64, cudaFuncAttributeMaxDynamicSharedMemorySize, G64_SMEM);
    cudaFuncSetAttribute(leaf_fused,   cudaFuncAttributeMaxDynamicSharedMemorySize, LF_SMEM);

    float *pC, *pFH, *pG, *pbn;
    hlf *pXh, *pXl, *pCh, *pCl, *pXHh, *pXHl, *pWnh, *pWfhh;
    cudaGetSymbolAddress((void**)&pC,    g_C);
    cudaGetSymbolAddress((void**)&pFH,   g_FH);
    cudaGetSymbolAddress((void**)&pG,    g_G);
    cudaGetSymbolAddress((void**)&pbn,   g_bnode);
    cudaGetSymbolAddress((void**)&pXh,   g_Xh);
    cudaGetSymbolAddress((void**)&pXl,   g_Xl);
    cudaGetSymbolAddress((void**)&pCh,   g_Ch);
    cudaGetSymbolAddress((void**)&pCl,   g_Cl);
    cudaGetSymbolAddress((void**)&pXHh,  g_XHh);
    cudaGetSymbolAddress((void**)&pXHl,  g_XHl);
    cudaGetSymbolAddress((void**)&pWnh,  g_Wnh);
    cudaGetSymbolAddress((void**)&pWfhh, g_Wfhh);

    static const int offs[6]  = {0, 1, 17, 273, 4369, 69905};
    static const int sizes[5] = {1, 16, 256, 4096, 65536};

    // 1) weights -> fp16
    pack_weights<<<(2048 * 1024 + 255) / 256, 256>>>(wi_w, wi_b, wf_w, wf_b,
                                                     wo_w, wo_b, wu_w, wu_b);
    // 2) leaf x -> split fp16
    split4<<<(NLEAF * IN_DIM / 4 + 255) / 256, 256>>>(x + (size_t)offs[4] * IN_DIM,
                                                      pXh, pXl, NLEAF * IN_DIM / 4);
    // 3) fused leaf gates (writes C,H,Ch,Cl), then FH GEMM
    {
        dim3 grid(HID / 64, NLEAF / 128);
        leaf_fused<<<grid, 512, LF_SMEM>>>(pXh, pXl);
    }
    launch_gemm(pCh + (size_t)offs[4] * HID, pCl + (size_t)offs[4] * HID,
                pWfhh, pFH + (size_t)offs[4] * HID, nullptr, NLEAF, 512, 512);

    // 4) internal levels, bottom-up
    for (int d = 3; d >= 0; d--) {
        int n = sizes[d];
        concat_xh4<<<(n * 256 + 255) / 256, 256>>>(x, offs[d], offs[d + 1], n);
        launch_gemm(pXHh, pXHl, pWnh, pG, pbn, n, 2048, 1024);
        node_epilogue4<<<(n * 128 + 255) / 256, 256>>>(offs[d], offs[d + 1], n);
        if (d > 0)
            launch_gemm(pCh + (size_t)offs[d] * HID, pCl + (size_t)offs[d] * HID,
                        pWfhh, pFH + (size_t)offs[d] * HID, nullptr, n, 512, 512);
    }

    // 5) output: H[0] then C[0]
    writeout<<<4, 256>>>(out);
}

// round 9
// speedup vs baseline: 1.9488x; 1.4047x over previous
#include <cuda_runtime.h>
#include <cuda_fp16.h>
#include <math.h>
#include <stdint.h>

// ---------------------------------------------------------------------------
// CSTreeLSTM on GB300: single-term fp16 HMMA GEMMs (fp32 accumulate).
// C ~= Ah @ Bh^T with A,B rounded to fp16 (rel err ~2^-12 each side).
// Tree: 16-ary, depth 4, IN=HID=512. Levels 1,16,256,4096,65536
// (offsets 0,1,17,273,4369; total 69905).
// ---------------------------------------------------------------------------

#define IN_DIM 512
#define HID    512
#define NLEAF  65536
#define NTOT   69905

typedef __half hlf;

// ------------------------------ device scratch ------------------------------
__device__ __align__(128) float g_C [NTOT * HID];
__device__ __align__(128) float g_H [NTOT * HID];
__device__ __align__(128) float g_FH[NTOT * HID];
__device__ __align__(128) float g_G [4096 * 2048];   // node-level gates only

__device__ __align__(128) hlf g_Xh [NLEAF * IN_DIM];
__device__ __align__(128) hlf g_Ch [NTOT * HID];
__device__ __align__(128) hlf g_XHh[4096 * 1024];

__device__ __align__(128) hlf g_Wnh[2048 * 1024];
__device__ __align__(128) hlf g_Wlh[1536 * 512];
__device__ __align__(128) hlf g_Wfhh[512 * 512];
__device__ float g_bleaf[1536];
__device__ float g_bnode[2048];

__device__ __forceinline__ float sigf(float x) { return 1.f / (1.f + expf(-x)); }

// ------------------------------ PTX helpers ---------------------------------
__device__ __forceinline__ uint32_t smem_u32(const void* p) {
    uint32_t a;
    asm("{ .reg .u64 t; cvta.to.shared.u64 t, %1; cvt.u32.u64 %0, t; }" : "=r"(a) : "l"(p));
    return a;
}

__device__ __forceinline__ void cp16(uint32_t dst, const void* src) {
    asm volatile("cp.async.cg.shared.global [%0], [%1], 16;" :: "r"(dst), "l"(src));
}
#define CP_COMMIT() asm volatile("cp.async.commit_group;" ::: "memory")

__device__ __forceinline__ void ldsm4(uint32_t* r, uint32_t addr) {
    asm volatile("ldmatrix.sync.aligned.m8n8.x4.shared.b16 {%0,%1,%2,%3}, [%4];"
                 : "=r"(r[0]), "=r"(r[1]), "=r"(r[2]), "=r"(r[3]) : "r"(addr));
}
__device__ __forceinline__ void mma16816(float* d, const uint32_t* a, const uint32_t* b) {
    asm volatile(
        "mma.sync.aligned.m16n8k16.row.col.f32.f16.f16.f32 "
        "{%0,%1,%2,%3}, {%4,%5,%6,%7}, {%8,%9}, {%0,%1,%2,%3};"
        : "+f"(d[0]), "+f"(d[1]), "+f"(d[2]), "+f"(d[3])
        : "r"(a[0]), "r"(a[1]), "r"(a[2]), "r"(a[3]), "r"(b[0]), "r"(b[1]));
}

// ---------------------------------------------------------------------------
// Fused leaf kernel. CTA tile: 128(M) x 64(h), 3 gates. 512 threads,
// 16 warps, warp tile 32x16 per gate, BK=32, 3 stages. M%128==0, K=512.
// ---------------------------------------------------------------------------
#define LF_PITCH 80
#define LF_AT (128 * LF_PITCH)             // 10240
#define LF_BT (64 * LF_PITCH)              // 5120
#define LF_STAGE (LF_AT + 3 * LF_BT)       // 25600
#define LF_SMEM (3 * LF_STAGE + 128)

__global__ __launch_bounds__(512)
void leaf_fused(const hlf* __restrict__ Ah) {
    extern __shared__ char smem_raw[];
    const uint32_t sbase = (smem_u32(smem_raw) + 127) & ~127u;

    const int tid  = threadIdx.x;
    const int lane = tid & 31;
    const int wid  = tid >> 5;
    const int wm   = wid >> 2;
    const int wn   = wid & 3;
    const int bm   = blockIdx.y * 128;
    const int bh   = blockIdx.x * 64;
    const int K    = 512;
    const int NC   = 16;

    const int ag = lane >> 3, ai = lane & 7;
    const int a_row = ai + (ag & 1) * 8;
    const int a_kb  = (ag >> 1) * 16;
    const int b_row2 = (lane & 7) + ((lane >> 4) << 3);
    const int b_kb   = ((lane >> 3) & 1) * 16;

    float acc[3][2][2][4];
#pragma unroll
    for (int g = 0; g < 3; g++)
#pragma unroll
        for (int mt = 0; mt < 2; mt++)
#pragma unroll
            for (int nt = 0; nt < 2; nt++)
#pragma unroll
                for (int j = 0; j < 4; j++) acc[g][mt][nt][j] = 0.f;

    auto load_chunk = [&](int c, int s) {
        const uint32_t sb = sbase + s * LF_STAGE;
        const int k0 = c << 5;
        {   // A tile: 512 positions, 1/thread
            int row = tid >> 2, cb = tid & 3;
            size_t aoff = (size_t)(bm + row) * K + k0 + cb * 8;
            cp16(sb + row * LF_PITCH + cb * 16, Ah + aoff);
        }
        // B (3 gates x 256 positions = 768)
#pragma unroll
        for (int i = 0; i < 2; ++i) {
            int p = tid + i * 512;
            if (p < 768) {
                int g = p >> 8, pp = p & 255;
                int row = pp >> 2, cb = pp & 3;
                size_t woff = (size_t)(g * 512 + bh + row) * 512 + k0 + cb * 8;
                cp16(sb + LF_AT + g * LF_BT + row * LF_PITCH + cb * 16, g_Wlh + woff);
            }
        }
        CP_COMMIT();
    };

    load_chunk(0, 0);
    load_chunk(1, 1);

    for (int c = 0; c < NC; ++c) {
        if (c + 2 < NC) load_chunk(c + 2, (c + 2) % 3);

        if (c + 2 < NC)      asm volatile("cp.async.wait_group 2;" ::: "memory");
        else if (c + 1 < NC) asm volatile("cp.async.wait_group 1;" ::: "memory");
        else                 asm volatile("cp.async.wait_group 0;" ::: "memory");
        __syncthreads();

        const uint32_t sb = sbase + (c % 3) * LF_STAGE;

#pragma unroll
        for (int ks = 0; ks < 2; ++ks) {
            const int kb = ks * 32;
            uint32_t ah[2][4];
#pragma unroll
            for (int mt = 0; mt < 2; ++mt) {
                uint32_t ro = (wm * 32 + mt * 16 + a_row) * LF_PITCH + a_kb + kb;
                ldsm4(ah[mt], sb + ro);
            }
            uint32_t bg[3][4];
#pragma unroll
            for (int g = 0; g < 3; ++g) {
                uint32_t ro = (wn * 16 + b_row2) * LF_PITCH + b_kb + kb;
                ldsm4(bg[g], sb + LF_AT + g * LF_BT + ro);
            }
#pragma unroll
            for (int g = 0; g < 3; ++g)
#pragma unroll
                for (int mt = 0; mt < 2; ++mt)
#pragma unroll
                    for (int nt = 0; nt < 2; ++nt)
                        mma16816(acc[g][mt][nt], ah[mt], &bg[g][nt * 2]);
        }
        __syncthreads();
    }

    const int r0 = lane >> 2;
    const int q2 = (lane & 3) * 2;
#pragma unroll
    for (int mt = 0; mt < 2; ++mt) {
#pragma unroll
        for (int nt = 0; nt < 2; ++nt) {
            int col = bh + wn * 16 + nt * 8 + q2;
            float bi0 = g_bleaf[col],        bi1 = g_bleaf[col + 1];
            float bo0 = g_bleaf[512 + col],  bo1 = g_bleaf[512 + col + 1];
            float bu0 = g_bleaf[1024 + col], bu1 = g_bleaf[1024 + col + 1];
#pragma unroll
            for (int hf = 0; hf < 2; ++hf) {
                int row = bm + wm * 32 + mt * 16 + r0 + hf * 8;
                float i0 = sigf(acc[0][mt][nt][hf * 2 + 0] + bi0);
                float i1 = sigf(acc[0][mt][nt][hf * 2 + 1] + bi1);
                float o0 = sigf(acc[1][mt][nt][hf * 2 + 0] + bo0);
                float o1 = sigf(acc[1][mt][nt][hf * 2 + 1] + bo1);
                float u0 = tanhf(acc[2][mt][nt][hf * 2 + 0] + bu0);
                float u1 = tanhf(acc[2][mt][nt][hf * 2 + 1] + bu1);
                float c0 = i0 * u0, c1 = i1 * u1;
                float h0 = o0 * tanhf(c0), h1 = o1 * tanhf(c1);
                size_t gi = (size_t)(4369 + row) * HID + col;
                *(float2*)(g_C + gi) = make_float2(c0, c1);
                *(float2*)(g_H + gi) = make_float2(h0, h1);
                __half2 vh; vh.x = __float2half_rn(c0); vh.y = __float2half_rn(c1);
                *(__half2*)(g_Ch + gi) = vh;
            }
        }
    }
}

// ---------------------------------------------------------------------------
// fp16 GEMM, CTA 128(M) x 256(N), 512 threads / 16 warps, warp tile 32x64,
// BK=32, 3-stage cp.async. N%256==0, K%32==0; M guarded.
// ---------------------------------------------------------------------------
#define TPITCH 80
#define AT_B (128 * TPITCH)            // 10240
#define BT_B (256 * TPITCH)            // 20480
#define STAGE_B (AT_B + BT_B)          // 30720
#define GSMEM (3 * STAGE_B + 128)

__global__ __launch_bounds__(512)
void gemm_h(const hlf* __restrict__ Ah, const hlf* __restrict__ Bh,
            float* __restrict__ C, const float* __restrict__ bias,
            int M, int N, int K) {
    extern __shared__ char smem_raw[];
    const uint32_t sbase = (smem_u32(smem_raw) + 127) & ~127u;

    const int tid  = threadIdx.x;
    const int lane = tid & 31;
    const int wid  = tid >> 5;
    const int wm   = wid >> 2;
    const int wn   = wid & 3;
    const int bm   = blockIdx.y * 128;
    const int bn   = blockIdx.x * 256;
    const int NC   = K >> 5;

    const int ag = lane >> 3, ai = lane & 7;
    const int a_row = ai + (ag & 1) * 8;
    const int a_kb  = (ag >> 1) * 16;
    const int b_row2 = (lane & 7) + ((lane >> 4) << 3);
    const int b_kb   = ((lane >> 3) & 1) * 16;

    float acc[2][8][4];
#pragma unroll
    for (int mt = 0; mt < 2; mt++)
#pragma unroll
        for (int nt = 0; nt < 8; nt++)
#pragma unroll
            for (int j = 0; j < 4; j++) acc[mt][nt][j] = 0.f;

    auto load_chunk = [&](int c, int s) {
        const uint32_t sb = sbase + s * STAGE_B;
        const int k0 = c << 5;
        {
            int row = tid >> 2, cb = tid & 3;
            int ar = bm + row; if (ar > M - 1) ar = M - 1;
            size_t aoff = (size_t)ar * K + k0 + cb * 8;
            cp16(sb + row * TPITCH + cb * 16, Ah + aoff);
        }
#pragma unroll
        for (int i = 0; i < 2; ++i) {
            int p = tid + i * 512;
            int row = p >> 2, cb = p & 3;
            size_t boff = (size_t)(bn + row) * K + k0 + cb * 8;
            cp16(sb + AT_B + row * TPITCH + cb * 16, Bh + boff);
        }
        CP_COMMIT();
    };

    load_chunk(0, 0);
    if (NC > 1) load_chunk(1, 1);

    for (int c = 0; c < NC; ++c) {
        if (c + 2 < NC) load_chunk(c + 2, (c + 2) % 3);

        if (c + 2 < NC)      asm volatile("cp.async.wait_group 2;" ::: "memory");
        else if (c + 1 < NC) asm volatile("cp.async.wait_group 1;" ::: "memory");
        else                 asm volatile("cp.async.wait_group 0;" ::: "memory");
        __syncthreads();

        const uint32_t sb  = sbase + (c % 3) * STAGE_B;
        const uint32_t tAh = sb, tBh = sb + AT_B;

#pragma unroll
        for (int ks = 0; ks < 2; ++ks) {
            const int kb = ks * 32;
            uint32_t ah[2][4], bh[8][2];
#pragma unroll
            for (int mt = 0; mt < 2; ++mt) {
                uint32_t ro = (wm * 32 + mt * 16 + a_row) * TPITCH + a_kb + kb;
                ldsm4(ah[mt], tAh + ro);
            }
#pragma unroll
            for (int nt2 = 0; nt2 < 8; nt2 += 2) {
                uint32_t ro = (wn * 64 + nt2 * 8 + b_row2) * TPITCH + b_kb + kb;
                ldsm4(&bh[nt2][0], tBh + ro);
            }
#pragma unroll
            for (int mt = 0; mt < 2; ++mt)
#pragma unroll
                for (int nt = 0; nt < 8; ++nt)
                    mma16816(acc[mt][nt], ah[mt], bh[nt]);
        }
        __syncthreads();
    }

    const int r0 = lane >> 2;
    const int q2 = (lane & 3) * 2;
#pragma unroll
    for (int mt = 0; mt < 2; ++mt) {
        int row = bm + wm * 32 + mt * 16 + r0;
#pragma unroll
        for (int nt = 0; nt < 8; ++nt) {
            int col = bn + wn * 64 + nt * 8 + q2;
            float bx = 0.f, by = 0.f;
            if (bias) { bx = bias[col]; by = bias[col + 1]; }
            if (row < M)
                *(float2*)(C + (size_t)row * N + col) =
                    make_float2(acc[mt][nt][0] + bx, acc[mt][nt][1] + by);
            if (row + 8 < M)
                *(float2*)(C + (size_t)(row + 8) * N + col) =
                    make_float2(acc[mt][nt][2] + bx, acc[mt][nt][3] + by);
        }
    }
}

// ---------------------------------------------------------------------------
// fp16 GEMM, CTA 64x64 (small M tail). 128 threads, 4 warps 32x32.
// ---------------------------------------------------------------------------
#define G64_T (64 * TPITCH)
#define G64_STAGE (2 * G64_T)
#define G64_SMEM (3 * G64_STAGE + 128)

__global__ __launch_bounds__(128)
void gemm_h64(const hlf* __restrict__ Ah, const hlf* __restrict__ Bh,
              float* __restrict__ C, const float* __restrict__ bias,
              int M, int N, int K) {
    extern __shared__ char smem_raw[];
    const uint32_t sbase = (smem_u32(smem_raw) + 127) & ~127u;

    const int tid  = threadIdx.x;
    const int lane = tid & 31;
    const int wid  = tid >> 5;
    const int wm   = wid >> 1;
    const int wn   = wid & 1;
    const int bm   = blockIdx.y * 64;
    const int bn   = blockIdx.x * 64;
    const int NC   = K >> 5;

    const int ag = lane >> 3, ai = lane & 7;
    const int a_row = ai + (ag & 1) * 8;
    const int a_kb  = (ag >> 1) * 16;
    const int b_row2 = (lane & 7) + ((lane >> 4) << 3);
    const int b_kb   = ((lane >> 3) & 1) * 16;

    float acc[2][4][4];
#pragma unroll
    for (int mt = 0; mt < 2; mt++)
#pragma unroll
        for (int nt = 0; nt < 4; nt++)
#pragma unroll
            for (int j = 0; j < 4; j++) acc[mt][nt][j] = 0.f;

    auto load_chunk = [&](int c, int s) {
        const uint32_t sb = sbase + s * G64_STAGE;
        const int k0 = c << 5;
#pragma unroll
        for (int it = 0; it < 2; ++it) {
            int idx = tid + it * 128;
            int row = idx >> 2, cb = idx & 3;
            int ar = bm + row; if (ar > M - 1) ar = M - 1;
            size_t aoff = (size_t)ar * K + k0 + cb * 8;
            size_t boff = (size_t)(bn + row) * K + k0 + cb * 8;
            uint32_t so = row * TPITCH + cb * 16;
            cp16(sb + so,         Ah + aoff);
            cp16(sb + G64_T + so, Bh + boff);
        }
        CP_COMMIT();
    };

    load_chunk(0, 0);
    if (NC > 1) load_chunk(1, 1);

    for (int c = 0; c < NC; ++c) {
        if (c + 2 < NC) load_chunk(c + 2, (c + 2) % 3);

        if (c + 2 < NC)      asm volatile("cp.async.wait_group 2;" ::: "memory");
        else if (c + 1 < NC) asm volatile("cp.async.wait_group 1;" ::: "memory");
        else                 asm volatile("cp.async.wait_group 0;" ::: "memory");
        __syncthreads();

        const uint32_t sb  = sbase + (c % 3) * G64_STAGE;
        const uint32_t tAh = sb, tBh = sb + G64_T;

#pragma unroll
        for (int ks = 0; ks < 2; ++ks) {
            const int kb = ks * 32;
            uint32_t ah[2][4], bh[4][2];
#pragma unroll
            for (int mt = 0; mt < 2; ++mt) {
                uint32_t ro = (wm * 32 + mt * 16 + a_row) * TPITCH + a_kb + kb;
                ldsm4(ah[mt], tAh + ro);
            }
#pragma unroll
            for (int nt2 = 0; nt2 < 4; nt2 += 2) {
                uint32_t ro = (wn * 32 + nt2 * 8 + b_row2) * TPITCH + b_kb + kb;
                ldsm4(&bh[nt2][0], tBh + ro);
            }
#pragma unroll
            for (int mt = 0; mt < 2; ++mt)
#pragma unroll
                for (int nt = 0; nt < 4; ++nt)
                    mma16816(acc[mt][nt], ah[mt], bh[nt]);
        }
        __syncthreads();
    }

    const int r0 = lane >> 2;
    const int q2 = (lane & 3) * 2;
#pragma unroll
    for (int mt = 0; mt < 2; ++mt) {
        int row = bm + wm * 32 + mt * 16 + r0;
#pragma unroll
        for (int nt = 0; nt < 4; ++nt) {
            int col = bn + wn * 32 + nt * 8 + q2;
            float bx = 0.f, by = 0.f;
            if (bias) { bx = bias[col]; by = bias[col + 1]; }
            if (row < M)
                *(float2*)(C + (size_t)row * N + col) =
                    make_float2(acc[mt][nt][0] + bx, acc[mt][nt][1] + by);
            if (row + 8 < M)
                *(float2*)(C + (size_t)(row + 8) * N + col) =
                    make_float2(acc[mt][nt][2] + bx, acc[mt][nt][3] + by);
        }
    }
}

// ---------------------------------------------------------------------------
// Weight packing (fp32 -> fp16) + biases
// ---------------------------------------------------------------------------
__global__ void pack_weights(const float* __restrict__ wi_w, const float* __restrict__ wi_b,
                             const float* __restrict__ wf_w, const float* __restrict__ wf_b,
                             const float* __restrict__ wo_w, const float* __restrict__ wo_b,
                             const float* __restrict__ wu_w, const float* __restrict__ wu_b) {
    int idx = blockIdx.x * blockDim.x + threadIdx.x;

    if (idx < 2048 * 1024) {
        int r = idx >> 10, k = idx & 1023;
        float v;
        if      (r <  512) v = wi_w[r * 1024 + k];
        else if (r < 1024) v = wo_w[(r -  512) * 1024 + k];
        else if (r < 1536) v = wu_w[(r - 1024) * 1024 + k];
        else               v = (k < 512) ? wf_w[(r - 1536) * 1024 + k] : 0.f;
        g_Wnh[idx] = __float2half_rn(v);
    }
    if (idx < 1536 * 512) {
        int r = idx >> 9, k = idx & 511;
        float v;
        if      (r <  512) v = wi_w[r * 1024 + k];
        else if (r < 1024) v = wo_w[(r -  512) * 1024 + k];
        else               v = wu_w[(r - 1024) * 1024 + k];
        g_Wlh[idx] = __float2half_rn(v);
    }
    if (idx < 512 * 512) {
        int r = idx >> 9, k = idx & 511;
        g_Wfhh[idx] = __float2half_rn(wf_w[r * 1024 + 512 + k]);
    }
    if (idx < 1536)
        g_bleaf[idx] = (idx < 512) ? wi_b[idx] : (idx < 1024) ? wo_b[idx - 512] : wu_b[idx - 1024];
    if (idx < 2048)
        g_bnode[idx] = (idx <  512) ? wi_b[idx]
                     : (idx < 1024) ? wo_b[idx -  512]
                     : (idx < 1536) ? wu_b[idx - 1024] : wf_b[idx - 1536];
}

// fp32 -> fp16, 4 elems/thread
__global__ void cvt4(const float* __restrict__ src, hlf* __restrict__ h, int n4) {
    int i = blockIdx.x * blockDim.x + threadIdx.x;
    if (i >= n4) return;
    float4 v = ((const float4*)src)[i];
    hlf hh[4];
    hh[0] = __float2half_rn(v.x); hh[1] = __float2half_rn(v.y);
    hh[2] = __float2half_rn(v.z); hh[3] = __float2half_rn(v.w);
    ((uint2*)h)[i] = *(uint2*)hh;
}

// ---------------------------------------------------------------------------
// Elementwise stages (float4 vectorized)
// ---------------------------------------------------------------------------
__global__ void concat_xh4(const float* __restrict__ x, int off_d, int off_c, int n) {
    int idx = blockIdx.x * blockDim.x + threadIdx.x;
    if (idx >= n * 256) return;
    int r = idx >> 8, c4 = (idx & 255) * 4;
    float4 v;
    if (c4 < 512) {
        v = *(const float4*)(x + (size_t)(off_d + r) * IN_DIM + c4);
    } else {
        int hc = c4 - 512;
        size_t base = (size_t)(off_c + r * 16) * HID + hc;
        v = make_float4(0.f, 0.f, 0.f, 0.f);
#pragma unroll
        for (int k = 0; k < 16; k++) {
            float4 t = *(const float4*)(g_H + base + k * HID);
            v.x += t.x; v.y += t.y; v.z += t.z; v.w += t.w;
        }
    }
    hlf hh[4];
    hh[0] = __float2half_rn(v.x); hh[1] = __float2half_rn(v.y);
    hh[2] = __float2half_rn(v.z); hh[3] = __float2half_rn(v.w);
    *(uint2*)(g_XHh + (size_t)r * 1024 + c4) = *(uint2*)hh;
}

__global__ void node_epilogue4(int off_d, int off_c, int n) {
    int idx = blockIdx.x * blockDim.x + threadIdx.x;
    if (idx >= n * 128) return;
    int r = idx >> 7, h4 = (idx & 127) * 4;
    const float* g = g_G + (size_t)r * 2048;
    float4 gi = *(const float4*)(g + h4);
    float4 go = *(const float4*)(g + 512 + h4);
    float4 gu = *(const float4*)(g + 1024 + h4);
    float4 gf = *(const float4*)(g + 1536 + h4);
    float a0 = sigf(gi.x) * tanhf(gu.x);
    float a1 = sigf(gi.y) * tanhf(gu.y);
    float a2 = sigf(gi.z) * tanhf(gu.z);
    float a3 = sigf(gi.w) * tanhf(gu.w);
    size_t cb = (size_t)(off_c + r * 16) * HID + h4;
#pragma unroll
    for (int k = 0; k < 16; k++) {
        float4 fh = *(const float4*)(g_FH + cb + k * HID);
        float4 cc = *(const float4*)(g_C  + cb + k * HID);
        a0 += sigf(gf.x + fh.x) * cc.x;
        a1 += sigf(gf.y + fh.y) * cc.y;
        a2 += sigf(gf.z + fh.z) * cc.z;
        a3 += sigf(gf.w + fh.w) * cc.w;
    }
    size_t gidx = (size_t)(off_d + r) * HID + h4;
    *(float4*)(g_C + gidx) = make_float4(a0, a1, a2, a3);
    float4 hv = make_float4(sigf(go.x) * tanhf(a0), sigf(go.y) * tanhf(a1),
                            sigf(go.z) * tanhf(a2), sigf(go.w) * tanhf(a3));
    *(float4*)(g_H + gidx) = hv;
    hlf hh[4];
    hh[0] = __float2half_rn(a0); hh[1] = __float2half_rn(a1);
    hh[2] = __float2half_rn(a2); hh[3] = __float2half_rn(a3);
    *(uint2*)(g_Ch + gidx) = *(uint2*)hh;
}

__global__ void writeout(float* __restrict__ out) {
    int idx = blockIdx.x * blockDim.x + threadIdx.x;
    if (idx < 512)       out[idx] = g_H[idx];
    else if (idx < 1024) out[idx] = g_C[idx - 512];
}

// ---------------------------------------------------------------------------
// Launch
// ---------------------------------------------------------------------------
static void launch_gemm(const hlf* Ah, const hlf* Bh,
                        float* C, const float* bias, int M, int N, int K) {
    if (M >= 1024) {
        dim3 grid(N / 256, (M + 127) / 128);
        gemm_h<<<grid, 512, GSMEM>>>(Ah, Bh, C, bias, M, N, K);
    } else {
        dim3 grid(N / 64, (M + 63) / 64);
        gemm_h64<<<grid, 128, G64_SMEM>>>(Ah, Bh, C, bias, M, N, K);
    }
}

extern "C" void kernel_launch(void* const* d_in, const int* in_sizes, int n_in,
                              void* d_out, int out_size) {
    const float* x    = (const float*)d_in[0];
    const float* wi_w = (const float*)d_in[1];
    const float* wi_b = (const float*)d_in[2];
    const float* wf_w = (const float*)d_in[3];
    const float* wf_b = (const float*)d_in[4];
    const float* wo_w = (const float*)d_in[5];
    const float* wo_b = (const float*)d_in[6];
    const float* wu_w = (const float*)d_in[7];
    const float* wu_b = (const float*)d_in[8];
    float* out = (float*)d_out;

    cudaFuncSetAttribute(gemm_h,     cudaFuncAttributeMaxDynamicSharedMemorySize, GSMEM);
    cudaFuncSetAttribute(gemm_h64,   cudaFuncAttributeMaxDynamicSharedMemorySize, G64_SMEM);
    cudaFuncSetAttribute(leaf_fused, cudaFuncAttributeMaxDynamicSharedMemorySize, LF_SMEM);

    float *pC, *pFH, *pG, *pbn;
    hlf *pXh, *pCh, *pXHh, *pWnh, *pWfhh;
    cudaGetSymbolAddress((void**)&pC,    g_C);
    cudaGetSymbolAddress((void**)&pFH,   g_FH);
    cudaGetSymbolAddress((void**)&pG,    g_G);
    cudaGetSymbolAddress((void**)&pbn,   g_bnode);
    cudaGetSymbolAddress((void**)&pXh,   g_Xh);
    cudaGetSymbolAddress((void**)&pCh,   g_Ch);
    cudaGetSymbolAddress((void**)&pXHh,  g_XHh);
    cudaGetSymbolAddress((void**)&pWnh,  g_Wnh);
    cudaGetSymbolAddress((void**)&pWfhh, g_Wfhh);

    static const int offs[6]  = {0, 1, 17, 273, 4369, 69905};
    static const int sizes[5] = {1, 16, 256, 4096, 65536};

    // 1) weights -> fp16
    pack_weights<<<(2048 * 1024 + 255) / 256, 256>>>(wi_w, wi_b, wf_w, wf_b,
                                                     wo_w, wo_b, wu_w, wu_b);
    // 2) leaf x -> fp16
    cvt4<<<(NLEAF * IN_DIM / 4 + 255) / 256, 256>>>(x + (size_t)offs[4] * IN_DIM,
                                                    pXh, NLEAF * IN_DIM / 4);
    // 3) fused leaf gates (writes C,H,Ch), then FH GEMM
    {
        dim3 grid(HID / 64, NLEAF / 128);
        leaf_fused<<<grid, 512, LF_SMEM>>>(pXh);
    }
    launch_gemm(pCh + (size_t)offs[4] * HID, pWfhh,
                pFH + (size_t)offs[4] * HID, nullptr, NLEAF, 512, 512);

    // 4) internal levels, bottom-up
    for (int d = 3; d >= 0; d--) {
        int n = sizes[d];
        concat_xh4<<<(n * 256 + 255) / 256, 256>>>(x, offs[d], offs[d + 1], n);
        launch_gemm(pXHh, pWnh, pG, pbn, n, 2048, 1024);
        node_epilogue4<<<(n * 128 + 255) / 256, 256>>>(offs[d], offs[d + 1], n);
        if (d > 0)
            launch_gemm(pCh + (size_t)offs[d] * HID, pWfhh,
                        pFH + (size_t)offs[d] * HID, nullptr, n, 512, 512);
    }

    // 5) output: H[0] then C[0]
    writeout<<<4, 256>>>(out);
}

// round 10
// speedup vs baseline: 1.9951x; 1.0237x over previous
#include <cuda_runtime.h>
#include <cuda_fp16.h>
#include <math.h>
#include <stdint.h>

// ---------------------------------------------------------------------------
// CSTreeLSTM on GB300: single-term fp16 HMMA GEMMs (fp32 accumulate),
// fp16 cross-kernel intermediates (Ch, Hh for leaves; FH everywhere).
// Tree: 16-ary, depth 4, IN=HID=512. Levels 1,16,256,4096,65536
// (offsets 0,1,17,273,4369; total 69905).
// ---------------------------------------------------------------------------

#define IN_DIM 512
#define HID    512
#define NLEAF  65536
#define NTOT   69905

typedef __half hlf;

// ------------------------------ device scratch ------------------------------
__device__ __align__(128) float g_C [NTOT * HID];    // internal nodes fp32
__device__ __align__(128) float g_H [NTOT * HID];    // internal nodes fp32
__device__ __align__(128) hlf   g_FHh[NTOT * HID];   // f-gate hidden preact, fp16
__device__ __align__(128) float g_G [4096 * 2048];   // node-level gates only

__device__ __align__(128) hlf g_Xh [NLEAF * IN_DIM];
__device__ __align__(128) hlf g_Ch [NTOT * HID];
__device__ __align__(128) hlf g_Hh [NLEAF * HID];    // leaf H, fp16
__device__ __align__(128) hlf g_XHh[4096 * 1024];

__device__ __align__(128) hlf g_Wnh[2048 * 1024];
__device__ __align__(128) hlf g_Wlh[1536 * 512];
__device__ __align__(128) hlf g_Wfhh[512 * 512];
__device__ float g_bleaf[1536];
__device__ float g_bnode[2048];

__device__ __forceinline__ float sigf(float x) { return 1.f / (1.f + expf(-x)); }

// ------------------------------ PTX helpers ---------------------------------
__device__ __forceinline__ uint32_t smem_u32(const void* p) {
    uint32_t a;
    asm("{ .reg .u64 t; cvta.to.shared.u64 t, %1; cvt.u32.u64 %0, t; }" : "=r"(a) : "l"(p));
    return a;
}

__device__ __forceinline__ void cp16(uint32_t dst, const void* src) {
    asm volatile("cp.async.cg.shared.global [%0], [%1], 16;" :: "r"(dst), "l"(src));
}
#define CP_COMMIT() asm volatile("cp.async.commit_group;" ::: "memory")

__device__ __forceinline__ void ldsm4(uint32_t* r, uint32_t addr) {
    asm volatile("ldmatrix.sync.aligned.m8n8.x4.shared.b16 {%0,%1,%2,%3}, [%4];"
                 : "=r"(r[0]), "=r"(r[1]), "=r"(r[2]), "=r"(r[3]) : "r"(addr));
}
__device__ __forceinline__ void mma16816(float* d, const uint32_t* a, const uint32_t* b) {
    asm volatile(
        "mma.sync.aligned.m16n8k16.row.col.f32.f16.f16.f32 "
        "{%0,%1,%2,%3}, {%4,%5,%6,%7}, {%8,%9}, {%0,%1,%2,%3};"
        : "+f"(d[0]), "+f"(d[1]), "+f"(d[2]), "+f"(d[3])
        : "r"(a[0]), "r"(a[1]), "r"(a[2]), "r"(a[3]), "r"(b[0]), "r"(b[1]));
}

// half2 <-> float helpers
__device__ __forceinline__ float4 h4_to_f4(uint2 u) {
    __half2 lo = *(__half2*)&u.x, hi = *(__half2*)&u.y;
    float2 a = __half22float2(lo), b = __half22float2(hi);
    return make_float4(a.x, a.y, b.x, b.y);
}

// ---------------------------------------------------------------------------
// Fused leaf kernel. CTA tile: 128(M) x 64(h), 3 gates. 512 threads,
// 16 warps, warp tile 32x16 per gate, BK=32, 3 stages. K=512.
// Writes ONLY Ch, Hh (fp16).
// ---------------------------------------------------------------------------
#define LF_PITCH 80
#define LF_AT (128 * LF_PITCH)
#define LF_BT (64 * LF_PITCH)
#define LF_STAGE (LF_AT + 3 * LF_BT)
#define LF_SMEM (3 * LF_STAGE + 128)

__global__ __launch_bounds__(512)
void leaf_fused(const hlf* __restrict__ Ah) {
    extern __shared__ char smem_raw[];
    const uint32_t sbase = (smem_u32(smem_raw) + 127) & ~127u;

    const int tid  = threadIdx.x;
    const int lane = tid & 31;
    const int wid  = tid >> 5;
    const int wm   = wid >> 2;
    const int wn   = wid & 3;
    const int bm   = blockIdx.y * 128;
    const int bh   = blockIdx.x * 64;
    const int K    = 512;
    const int NC   = 16;

    const int ag = lane >> 3, ai = lane & 7;
    const int a_row = ai + (ag & 1) * 8;
    const int a_kb  = (ag >> 1) * 16;
    const int b_row2 = (lane & 7) + ((lane >> 4) << 3);
    const int b_kb   = ((lane >> 3) & 1) * 16;

    float acc[3][2][2][4];
#pragma unroll
    for (int g = 0; g < 3; g++)
#pragma unroll
        for (int mt = 0; mt < 2; mt++)
#pragma unroll
            for (int nt = 0; nt < 2; nt++)
#pragma unroll
                for (int j = 0; j < 4; j++) acc[g][mt][nt][j] = 0.f;

    auto load_chunk = [&](int c, int s) {
        const uint32_t sb = sbase + s * LF_STAGE;
        const int k0 = c << 5;
        {
            int row = tid >> 2, cb = tid & 3;
            size_t aoff = (size_t)(bm + row) * K + k0 + cb * 8;
            cp16(sb + row * LF_PITCH + cb * 16, Ah + aoff);
        }
#pragma unroll
        for (int i = 0; i < 2; ++i) {
            int p = tid + i * 512;
            if (p < 768) {
                int g = p >> 8, pp = p & 255;
                int row = pp >> 2, cb = pp & 3;
                size_t woff = (size_t)(g * 512 + bh + row) * 512 + k0 + cb * 8;
                cp16(sb + LF_AT + g * LF_BT + row * LF_PITCH + cb * 16, g_Wlh + woff);
            }
        }
        CP_COMMIT();
    };

    load_chunk(0, 0);
    load_chunk(1, 1);

    for (int c = 0; c < NC; ++c) {
        if (c + 2 < NC) load_chunk(c + 2, (c + 2) % 3);

        if (c + 2 < NC)      asm volatile("cp.async.wait_group 2;" ::: "memory");
        else if (c + 1 < NC) asm volatile("cp.async.wait_group 1;" ::: "memory");
        else                 asm volatile("cp.async.wait_group 0;" ::: "memory");
        __syncthreads();

        const uint32_t sb = sbase + (c % 3) * LF_STAGE;

#pragma unroll
        for (int ks = 0; ks < 2; ++ks) {
            const int kb = ks * 32;
            uint32_t ah[2][4];
#pragma unroll
            for (int mt = 0; mt < 2; ++mt) {
                uint32_t ro = (wm * 32 + mt * 16 + a_row) * LF_PITCH + a_kb + kb;
                ldsm4(ah[mt], sb + ro);
            }
            uint32_t bg[3][4];
#pragma unroll
            for (int g = 0; g < 3; ++g) {
                uint32_t ro = (wn * 16 + b_row2) * LF_PITCH + b_kb + kb;
                ldsm4(bg[g], sb + LF_AT + g * LF_BT + ro);
            }
#pragma unroll
            for (int g = 0; g < 3; ++g)
#pragma unroll
                for (int mt = 0; mt < 2; ++mt)
#pragma unroll
                    for (int nt = 0; nt < 2; ++nt)
                        mma16816(acc[g][mt][nt], ah[mt], &bg[g][nt * 2]);
        }
        __syncthreads();
    }

    const int r0 = lane >> 2;
    const int q2 = (lane & 3) * 2;
#pragma unroll
    for (int mt = 0; mt < 2; ++mt) {
#pragma unroll
        for (int nt = 0; nt < 2; ++nt) {
            int col = bh + wn * 16 + nt * 8 + q2;
            float bi0 = g_bleaf[col],        bi1 = g_bleaf[col + 1];
            float bo0 = g_bleaf[512 + col],  bo1 = g_bleaf[512 + col + 1];
            float bu0 = g_bleaf[1024 + col], bu1 = g_bleaf[1024 + col + 1];
#pragma unroll
            for (int hf = 0; hf < 2; ++hf) {
                int row = bm + wm * 32 + mt * 16 + r0 + hf * 8;   // leaf index
                float i0 = sigf(acc[0][mt][nt][hf * 2 + 0] + bi0);
                float i1 = sigf(acc[0][mt][nt][hf * 2 + 1] + bi1);
                float o0 = sigf(acc[1][mt][nt][hf * 2 + 0] + bo0);
                float o1 = sigf(acc[1][mt][nt][hf * 2 + 1] + bo1);
                float u0 = tanhf(acc[2][mt][nt][hf * 2 + 0] + bu0);
                float u1 = tanhf(acc[2][mt][nt][hf * 2 + 1] + bu1);
                float c0 = i0 * u0, c1 = i1 * u1;
                float h0 = o0 * tanhf(c0), h1 = o1 * tanhf(c1);
                size_t gci = (size_t)(4369 + row) * HID + col;   // global node idx
                size_t ghi = (size_t)row * HID + col;            // leaf-local idx
                __half2 vc; vc.x = __float2half_rn(c0); vc.y = __float2half_rn(c1);
                __half2 vh; vh.x = __float2half_rn(h0); vh.y = __float2half_rn(h1);
                *(__half2*)(g_Ch + gci) = vc;
                *(__half2*)(g_Hh + ghi) = vh;
            }
        }
    }
}

// ---------------------------------------------------------------------------
// fp16 GEMM, CTA 128(M) x 256(N), 512 threads / 16 warps, warp tile 32x64,
// BK=32, 3-stage cp.async. N%256==0, K%32==0; M guarded.
// half_out: write __half (C cast to hlf*); else fp32.
// ---------------------------------------------------------------------------
#define TPITCH 80
#define AT_B (128 * TPITCH)
#define BT_B (256 * TPITCH)
#define STAGE_B (AT_B + BT_B)
#define GSMEM (3 * STAGE_B + 128)

__global__ __launch_bounds__(512)
void gemm_h(const hlf* __restrict__ Ah, const hlf* __restrict__ Bh,
            void* __restrict__ Cout, const float* __restrict__ bias,
            int M, int N, int K, int half_out) {
    extern __shared__ char smem_raw[];
    const uint32_t sbase = (smem_u32(smem_raw) + 127) & ~127u;

    const int tid  = threadIdx.x;
    const int lane = tid & 31;
    const int wid  = tid >> 5;
    const int wm   = wid >> 2;
    const int wn   = wid & 3;
    const int bm   = blockIdx.y * 128;
    const int bn   = blockIdx.x * 256;
    const int NC   = K >> 5;

    const int ag = lane >> 3, ai = lane & 7;
    const int a_row = ai + (ag & 1) * 8;
    const int a_kb  = (ag >> 1) * 16;
    const int b_row2 = (lane & 7) + ((lane >> 4) << 3);
    const int b_kb   = ((lane >> 3) & 1) * 16;

    float acc[2][8][4];
#pragma unroll
    for (int mt = 0; mt < 2; mt++)
#pragma unroll
        for (int nt = 0; nt < 8; nt++)
#pragma unroll
            for (int j = 0; j < 4; j++) acc[mt][nt][j] = 0.f;

    auto load_chunk = [&](int c, int s) {
        const uint32_t sb = sbase + s * STAGE_B;
        const int k0 = c << 5;
        {
            int row = tid >> 2, cb = tid & 3;
            int ar = bm + row; if (ar > M - 1) ar = M - 1;
            size_t aoff = (size_t)ar * K + k0 + cb * 8;
            cp16(sb + row * TPITCH + cb * 16, Ah + aoff);
        }
#pragma unroll
        for (int i = 0; i < 2; ++i) {
            int p = tid + i * 512;
            int row = p >> 2, cb = p & 3;
            size_t boff = (size_t)(bn + row) * K + k0 + cb * 8;
            cp16(sb + AT_B + row * TPITCH + cb * 16, Bh + boff);
        }
        CP_COMMIT();
    };

    load_chunk(0, 0);
    if (NC > 1) load_chunk(1, 1);

    for (int c = 0; c < NC; ++c) {
        if (c + 2 < NC) load_chunk(c + 2, (c + 2) % 3);

        if (c + 2 < NC)      asm volatile("cp.async.wait_group 2;" ::: "memory");
        else if (c + 1 < NC) asm volatile("cp.async.wait_group 1;" ::: "memory");
        else                 asm volatile("cp.async.wait_group 0;" ::: "memory");
        __syncthreads();

        const uint32_t sb  = sbase + (c % 3) * STAGE_B;
        const uint32_t tAh = sb, tBh = sb + AT_B;

#pragma unroll
        for (int ks = 0; ks < 2; ++ks) {
            const int kb = ks * 32;
            uint32_t ah[2][4], bh[8][2];
#pragma unroll
            for (int mt = 0; mt < 2; ++mt) {
                uint32_t ro = (wm * 32 + mt * 16 + a_row) * TPITCH + a_kb + kb;
                ldsm4(ah[mt], tAh + ro);
            }
#pragma unroll
            for (int nt2 = 0; nt2 < 8; nt2 += 2) {
                uint32_t ro = (wn * 64 + nt2 * 8 + b_row2) * TPITCH + b_kb + kb;
                ldsm4(&bh[nt2][0], tBh + ro);
            }
#pragma unroll
            for (int mt = 0; mt < 2; ++mt)
#pragma unroll
                for (int nt = 0; nt < 8; ++nt)
                    mma16816(acc[mt][nt], ah[mt], bh[nt]);
        }
        __syncthreads();
    }

    const int r0 = lane >> 2;
    const int q2 = (lane & 3) * 2;
#pragma unroll
    for (int mt = 0; mt < 2; ++mt) {
        int row = bm + wm * 32 + mt * 16 + r0;
#pragma unroll
        for (int nt = 0; nt < 8; ++nt) {
            int col = bn + wn * 64 + nt * 8 + q2;
            float bx = 0.f, by = 0.f;
            if (bias) { bx = bias[col]; by = bias[col + 1]; }
            float v00 = acc[mt][nt][0] + bx, v01 = acc[mt][nt][1] + by;
            float v10 = acc[mt][nt][2] + bx, v11 = acc[mt][nt][3] + by;
            if (half_out) {
                hlf* Ch = (hlf*)Cout;
                if (row < M) {
                    __half2 v; v.x = __float2half_rn(v00); v.y = __float2half_rn(v01);
                    *(__half2*)(Ch + (size_t)row * N + col) = v;
                }
                if (row + 8 < M) {
                    __half2 v; v.x = __float2half_rn(v10); v.y = __float2half_rn(v11);
                    *(__half2*)(Ch + (size_t)(row + 8) * N + col) = v;
                }
            } else {
                float* Cf = (float*)Cout;
                if (row < M)
                    *(float2*)(Cf + (size_t)row * N + col) = make_float2(v00, v01);
                if (row + 8 < M)
                    *(float2*)(Cf + (size_t)(row + 8) * N + col) = make_float2(v10, v11);
            }
        }
    }
}

// ---------------------------------------------------------------------------
// fp16 GEMM, CTA 64x64 (small M tail). 128 threads, 4 warps 32x32.
// ---------------------------------------------------------------------------
#define G64_T (64 * TPITCH)
#define G64_STAGE (2 * G64_T)
#define G64_SMEM (3 * G64_STAGE + 128)

__global__ __launch_bounds__(128)
void gemm_h64(const hlf* __restrict__ Ah, const hlf* __restrict__ Bh,
              void* __restrict__ Cout, const float* __restrict__ bias,
              int M, int N, int K, int half_out) {
    extern __shared__ char smem_raw[];
    const uint32_t sbase = (smem_u32(smem_raw) + 127) & ~127u;

    const int tid  = threadIdx.x;
    const int lane = tid & 31;
    const int wid  = tid >> 5;
    const int wm   = wid >> 1;
    const int wn   = wid & 1;
    const int bm   = blockIdx.y * 64;
    const int bn   = blockIdx.x * 64;
    const int NC   = K >> 5;

    const int ag = lane >> 3, ai = lane & 7;
    const int a_row = ai + (ag & 1) * 8;
    const int a_kb  = (ag >> 1) * 16;
    const int b_row2 = (lane & 7) + ((lane >> 4) << 3);
    const int b_kb   = ((lane >> 3) & 1) * 16;

    float acc[2][4][4];
#pragma unroll
    for (int mt = 0; mt < 2; mt++)
#pragma unroll
        for (int nt = 0; nt < 4; nt++)
#pragma unroll
            for (int j = 0; j < 4; j++) acc[mt][nt][j] = 0.f;

    auto load_chunk = [&](int c, int s) {
        const uint32_t sb = sbase + s * G64_STAGE;
        const int k0 = c << 5;
#pragma unroll
        for (int it = 0; it < 2; ++it) {
            int idx = tid + it * 128;
            int row = idx >> 2, cb = idx & 3;
            int ar = bm + row; if (ar > M - 1) ar = M - 1;
            size_t aoff = (size_t)ar * K + k0 + cb * 8;
            size_t boff = (size_t)(bn + row) * K + k0 + cb * 8;
            uint32_t so = row * TPITCH + cb * 16;
            cp16(sb + so,         Ah + aoff);
            cp16(sb + G64_T + so, Bh + boff);
        }
        CP_COMMIT();
    };

    load_chunk(0, 0);
    if (NC > 1) load_chunk(1, 1);

    for (int c = 0; c < NC; ++c) {
        if (c + 2 < NC) load_chunk(c + 2, (c + 2) % 3);

        if (c + 2 < NC)      asm volatile("cp.async.wait_group 2;" ::: "memory");
        else if (c + 1 < NC) asm volatile("cp.async.wait_group 1;" ::: "memory");
        else                 asm volatile("cp.async.wait_group 0;" ::: "memory");
        __syncthreads();

        const uint32_t sb  = sbase + (c % 3) * G64_STAGE;
        const uint32_t tAh = sb, tBh = sb + G64_T;

#pragma unroll
        for (int ks = 0; ks < 2; ++ks) {
            const int kb = ks * 32;
            uint32_t ah[2][4], bh[4][2];
#pragma unroll
            for (int mt = 0; mt < 2; ++mt) {
                uint32_t ro = (wm * 32 + mt * 16 + a_row) * TPITCH + a_kb + kb;
                ldsm4(ah[mt], tAh + ro);
            }
#pragma unroll
            for (int nt2 = 0; nt2 < 4; nt2 += 2) {
                uint32_t ro = (wn * 32 + nt2 * 8 + b_row2) * TPITCH + b_kb + kb;
                ldsm4(&bh[nt2][0], tBh + ro);
            }
#pragma unroll
            for (int mt = 0; mt < 2; ++mt)
#pragma unroll
                for (int nt = 0; nt < 4; ++nt)
                    mma16816(acc[mt][nt], ah[mt], bh[nt]);
        }
        __syncthreads();
    }

    const int r0 = lane >> 2;
    const int q2 = (lane & 3) * 2;
#pragma unroll
    for (int mt = 0; mt < 2; ++mt) {
        int row = bm + wm * 32 + mt * 16 + r0;
#pragma unroll
        for (int nt = 0; nt < 4; ++nt) {
            int col = bn + wn * 32 + nt * 8 + q2;
            float bx = 0.f, by = 0.f;
            if (bias) { bx = bias[col]; by = bias[col + 1]; }
            float v00 = acc[mt][nt][0] + bx, v01 = acc[mt][nt][1] + by;
            float v10 = acc[mt][nt][2] + bx, v11 = acc[mt][nt][3] + by;
            if (half_out) {
                hlf* Ch = (hlf*)Cout;
                if (row < M) {
                    __half2 v; v.x = __float2half_rn(v00); v.y = __float2half_rn(v01);
                    *(__half2*)(Ch + (size_t)row * N + col) = v;
                }
                if (row + 8 < M) {
                    __half2 v; v.x = __float2half_rn(v10); v.y = __float2half_rn(v11);
                    *(__half2*)(Ch + (size_t)(row + 8) * N + col) = v;
                }
            } else {
                float* Cf = (float*)Cout;
                if (row < M)
                    *(float2*)(Cf + (size_t)row * N + col) = make_float2(v00, v01);
                if (row + 8 < M)
                    *(float2*)(Cf + (size_t)(row + 8) * N + col) = make_float2(v10, v11);
            }
        }
    }
}

// ---------------------------------------------------------------------------
// Weight packing (fp32 -> fp16) + biases
// ---------------------------------------------------------------------------
__global__ void pack_weights(const float* __restrict__ wi_w, const float* __restrict__ wi_b,
                             const float* __restrict__ wf_w, const float* __restrict__ wf_b,
                             const float* __restrict__ wo_w, const float* __restrict__ wo_b,
                             const float* __restrict__ wu_w, const float* __restrict__ wu_b) {
    int idx = blockIdx.x * blockDim.x + threadIdx.x;

    if (idx < 2048 * 1024) {
        int r = idx >> 10, k = idx & 1023;
        float v;
        if      (r <  512) v = wi_w[r * 1024 + k];
        else if (r < 1024) v = wo_w[(r -  512) * 1024 + k];
        else if (r < 1536) v = wu_w[(r - 1024) * 1024 + k];
        else               v = (k < 512) ? wf_w[(r - 1536) * 1024 + k] : 0.f;
        g_Wnh[idx] = __float2half_rn(v);
    }
    if (idx < 1536 * 512) {
        int r = idx >> 9, k = idx & 511;
        float v;
        if      (r <  512) v = wi_w[r * 1024 + k];
        else if (r < 1024) v = wo_w[(r -  512) * 1024 + k];
        else               v = wu_w[(r - 1024) * 1024 + k];
        g_Wlh[idx] = __float2half_rn(v);
    }
    if (idx < 512 * 512) {
        int r = idx >> 9, k = idx & 511;
        g_Wfhh[idx] = __float2half_rn(wf_w[r * 1024 + 512 + k]);
    }
    if (idx < 1536)
        g_bleaf[idx] = (idx < 512) ? wi_b[idx] : (idx < 1024) ? wo_b[idx - 512] : wu_b[idx - 1024];
    if (idx < 2048)
        g_bnode[idx] = (idx <  512) ? wi_b[idx]
                     : (idx < 1024) ? wo_b[idx -  512]
                     : (idx < 1536) ? wu_b[idx - 1024] : wf_b[idx - 1536];
}

// fp32 -> fp16, 4 elems/thread
__global__ void cvt4(const float* __restrict__ src, hlf* __restrict__ h, int n4) {
    int i = blockIdx.x * blockDim.x + threadIdx.x;
    if (i >= n4) return;
    float4 v = ((const float4*)src)[i];
    hlf hh[4];
    hh[0] = __float2half_rn(v.x); hh[1] = __float2half_rn(v.y);
    hh[2] = __float2half_rn(v.z); hh[3] = __float2half_rn(v.w);
    ((uint2*)h)[i] = *(uint2*)hh;
}

// ---------------------------------------------------------------------------
// Elementwise stages
// ---------------------------------------------------------------------------
// leafkids: children are leaves -> read Hh fp16; else g_H fp32
__global__ void concat_xh4(const float* __restrict__ x, int off_d, int off_c,
                           int n, int leafkids) {
    int idx = blockIdx.x * blockDim.x + threadIdx.x;
    if (idx >= n * 256) return;
    int r = idx >> 8, c4 = (idx & 255) * 4;
    float4 v;
    if (c4 < 512) {
        v = *(const float4*)(x + (size_t)(off_d + r) * IN_DIM + c4);
    } else {
        int hc = c4 - 512;
        v = make_float4(0.f, 0.f, 0.f, 0.f);
        if (leafkids) {
            size_t base = (size_t)(off_c + r * 16 - 4369) * HID + hc;
#pragma unroll
            for (int k = 0; k < 16; k++) {
                float4 t = h4_to_f4(*(const uint2*)(g_Hh + base + k * HID));
                v.x += t.x; v.y += t.y; v.z += t.z; v.w += t.w;
            }
        } else {
            size_t base = (size_t)(off_c + r * 16) * HID + hc;
#pragma unroll
            for (int k = 0; k < 16; k++) {
                float4 t = *(const float4*)(g_H + base + k * HID);
                v.x += t.x; v.y += t.y; v.z += t.z; v.w += t.w;
            }
        }
    }
    hlf hh[4];
    hh[0] = __float2half_rn(v.x); hh[1] = __float2half_rn(v.y);
    hh[2] = __float2half_rn(v.z); hh[3] = __float2half_rn(v.w);
    *(uint2*)(g_XHh + (size_t)r * 1024 + c4) = *(uint2*)hh;
}

// leafkids: children C read from g_Ch fp16; else g_C fp32. FH always fp16.
__global__ void node_epilogue4(int off_d, int off_c, int n, int leafkids) {
    int idx = blockIdx.x * blockDim.x + threadIdx.x;
    if (idx >= n * 128) return;
    int r = idx >> 7, h4 = (idx & 127) * 4;
    const float* g = g_G + (size_t)r * 2048;
    float4 gi = *(const float4*)(g + h4);
    float4 go = *(const float4*)(g + 512 + h4);
    float4 gu = *(const float4*)(g + 1024 + h4);
    float4 gf = *(const float4*)(g + 1536 + h4);
    float a0 = sigf(gi.x) * tanhf(gu.x);
    float a1 = sigf(gi.y) * tanhf(gu.y);
    float a2 = sigf(gi.z) * tanhf(gu.z);
    float a3 = sigf(gi.w) * tanhf(gu.w);
    size_t cb = (size_t)(off_c + r * 16) * HID + h4;
#pragma unroll
    for (int k = 0; k < 16; k++) {
        float4 fh = h4_to_f4(*(const uint2*)(g_FHh + cb + k * HID));
        float4 cc;
        if (leafkids) cc = h4_to_f4(*(const uint2*)(g_Ch + cb + k * HID));
        else          cc = *(const float4*)(g_C + cb + k * HID);
        a0 += sigf(gf.x + fh.x) * cc.x;
        a1 += sigf(gf.y + fh.y) * cc.y;
        a2 += sigf(gf.z + fh.z) * cc.z;
        a3 += sigf(gf.w + fh.w) * cc.w;
    }
    size_t gidx = (size_t)(off_d + r) * HID + h4;
    *(float4*)(g_C + gidx) = make_float4(a0, a1, a2, a3);
    float4 hv = make_float4(sigf(go.x) * tanhf(a0), sigf(go.y) * tanhf(a1),
                            sigf(go.z) * tanhf(a2), sigf(go.w) * tanhf(a3));
    *(float4*)(g_H + gidx) = hv;
    hlf hh[4];
    hh[0] = __float2half_rn(a0); hh[1] = __float2half_rn(a1);
    hh[2] = __float2half_rn(a2); hh[3] = __float2half_rn(a3);
    *(uint2*)(g_Ch + gidx) = *(uint2*)hh;
}

__global__ void writeout(float* __restrict__ out) {
    int idx = blockIdx.x * blockDim.x + threadIdx.x;
    if (idx < 512)       out[idx] = g_H[idx];
    else if (idx < 1024) out[idx] = g_C[idx - 512];
}

// ---------------------------------------------------------------------------
// Launch
// ---------------------------------------------------------------------------
static void launch_gemm(const hlf* Ah, const hlf* Bh, void* Cout,
                        const float* bias, int M, int N, int K, int half_out) {
    if (M >= 1024) {
        dim3 grid(N / 256, (M + 127) / 128);
        gemm_h<<<grid, 512, GSMEM>>>(Ah, Bh, Cout, bias, M, N, K, half_out);
    } else {
        dim3 grid(N / 64, (M + 63) / 64);
        gemm_h64<<<grid, 128, G64_SMEM>>>(Ah, Bh, Cout, bias, M, N, K, half_out);
    }
}

extern "C" void kernel_launch(void* const* d_in, const int* in_sizes, int n_in,
                              void* d_out, int out_size) {
    const float* x    = (const float*)d_in[0];
    const float* wi_w = (const float*)d_in[1];
    const float* wi_b = (const float*)d_in[2];
    const float* wf_w = (const float*)d_in[3];
    const float* wf_b = (const float*)d_in[4];
    const float* wo_w = (const float*)d_in[5];
    const float* wo_b = (const float*)d_in[6];
    const float* wu_w = (const float*)d_in[7];
    const float* wu_b = (const float*)d_in[8];
    float* out = (float*)d_out;

    cudaFuncSetAttribute(gemm_h,     cudaFuncAttributeMaxDynamicSharedMemorySize, GSMEM);
    cudaFuncSetAttribute(gemm_h64,   cudaFuncAttributeMaxDynamicSharedMemorySize, G64_SMEM);
    cudaFuncSetAttribute(leaf_fused, cudaFuncAttributeMaxDynamicSharedMemorySize, LF_SMEM);

    float *pG, *pbn;
    hlf *pXh, *pCh, *pXHh, *pWnh, *pWfhh, *pFHh;
    cudaGetSymbolAddress((void**)&pG,    g_G);
    cudaGetSymbolAddress((void**)&pbn,   g_bnode);
    cudaGetSymbolAddress((void**)&pXh,   g_Xh);
    cudaGetSymbolAddress((void**)&pCh,   g_Ch);
    cudaGetSymbolAddress((void**)&pXHh,  g_XHh);
    cudaGetSymbolAddress((void**)&pWnh,  g_Wnh);
    cudaGetSymbolAddress((void**)&pWfhh, g_Wfhh);
    cudaGetSymbolAddress((void**)&pFHh,  g_FHh);

    static const int offs[6]  = {0, 1, 17, 273, 4369, 69905};
    static const int sizes[5] = {1, 16, 256, 4096, 65536};

    // 1) weights -> fp16
    pack_weights<<<(2048 * 1024 + 255) / 256, 256>>>(wi_w, wi_b, wf_w, wf_b,
                                                     wo_w, wo_b, wu_w, wu_b);
    // 2) leaf x -> fp16
    cvt4<<<(NLEAF * IN_DIM / 4 + 255) / 256, 256>>>(x + (size_t)offs[4] * IN_DIM,
                                                    pXh, NLEAF * IN_DIM / 4);
    // 3) fused leaf gates (writes Ch,Hh), then FH GEMM (fp16 out)
    {
        dim3 grid(HID / 64, NLEAF / 128);
        leaf_fused<<<grid, 512, LF_SMEM>>>(pXh);
    }
    launch_gemm(pCh + (size_t)offs[4] * HID, pWfhh,
                pFHh + (size_t)offs[4] * HID, nullptr, NLEAF, 512, 512, 1);

    // 4) internal levels, bottom-up
    for (int d = 3; d >= 0; d--) {
        int n = sizes[d];
        int leafkids = (d == 3) ? 1 : 0;
        concat_xh4<<<(n * 256 + 255) / 256, 256>>>(x, offs[d], offs[d + 1], n, leafkids);
        launch_gemm(pXHh, pWnh, pG, pbn, n, 2048, 1024, 0);
        node_epilogue4<<<(n * 128 + 255) / 256, 256>>>(offs[d], offs[d + 1], n, leafkids);
        if (d > 0)
            launch_gemm(pCh + (size_t)offs[d] * HID, pWfhh,
                        pFHh + (size_t)offs[d] * HID, nullptr, n, 512, 512, 1);
    }

    // 5) output: H[0] then C[0]
    writeout<<<4, 256>>>(out);
}